// round 1
// baseline (speedup 1.0000x reference)
#include <cuda_runtime.h>
#include <math.h>

#define B_      4
#define L_      2048
#define DMODEL  1024
#define DINNER  2048
#define DSTATE  64
#define KCONV   4
#define MTOT    (B_*L_)     // 8192
#define NOUT    128         // 2*DSTATE (x_ssm | dt)

// ---------------- scratch (device globals: no allocation allowed) ----------
__device__ float g_Abig[4*NOUT*DINNER];   // [512][2048]  P[j,c]*w[c,k]
__device__ float g_E[4*NOUT*DMODEL];      // [512][1024]  folded conv+in_proj+state-proj weights
__device__ float g_const[4*NOUT];         // per-boundary-position bias consts
__device__ float g_Ct[DMODEL*DSTATE];     // [1024][64]   folded D_mat*W_out^T
__device__ float g_dA[B_*DSTATE*L_];      // [b][s][l]
__device__ float g_dBx[B_*DSTATE*L_];     // [b][s][l]
__device__ float g_z[MTOT*DSTATE];        // [m][s]

// ---------------- prep: A_big[k*128+j, c] = P[j,c] * conv_w[c,k] -----------
__global__ void prep_abig(const float* __restrict__ Wx, const float* __restrict__ Wdt,
                          const float* __restrict__ convw){
    int idx = blockIdx.x*blockDim.x + threadIdx.x;
    const int total = 4*NOUT*DINNER;
    for (; idx < total; idx += gridDim.x*blockDim.x){
        int c   = idx & (DINNER-1);
        int row = idx >> 11;            // / 2048
        int k   = row >> 7;
        int j   = row & 127;
        float p = (j < DSTATE) ? Wx[j*DINNER + c] : Wdt[(j-DSTATE)*DINNER + c];
        g_Abig[idx] = p * convw[c*KCONV + k];
    }
}

// const_l[j] = bias_P[j] + sum_c P[j,c]*(conv_b[c] + b_in[c]*sum_{k>=3-l} w[c,k])
__global__ void prep_const(const float* __restrict__ Wx, const float* __restrict__ Wdt,
                           const float* __restrict__ convw, const float* __restrict__ convb,
                           const float* __restrict__ b_in, const float* __restrict__ b_x,
                           const float* __restrict__ b_dt){
    int j  = blockIdx.x;     // 0..127
    int lp = blockIdx.y;     // 0..3   (min(l,3))
    int t  = threadIdx.x;
    int kstart = 3 - lp;
    float partial = 0.f;
    for (int c = t; c < DINNER; c += 256){
        float sw = 0.f;
        #pragma unroll
        for (int k = 0; k < 4; k++) if (k >= kstart) sw += convw[c*4 + k];
        float p = (j < DSTATE) ? Wx[j*DINNER + c] : Wdt[(j-DSTATE)*DINNER + c];
        partial += p * (convb[c] + b_in[c]*sw);
    }
    __shared__ float red[256];
    red[t] = partial; __syncthreads();
    for (int s = 128; s > 0; s >>= 1){ if (t < s) red[t] += red[t+s]; __syncthreads(); }
    if (t == 0){
        float bias = (j < DSTATE) ? b_x[j] : b_dt[j-DSTATE];
        g_const[lp*NOUT + j] = red[0] + bias;
    }
}

// ---------------- generic tiled fp32 GEMM:  C = A * op(B) (+bias) ----------
// C[m,n] = sum_k A[m*lda+k] * (BT ? B[n*ldb+k] : B[k*ldb+n])
template<int BM,int BN,int BK,int TM,int TN,bool BT>
__global__ __launch_bounds__((BM/TM)*(BN/TN))
void gemm_nt(const float* __restrict__ A, const float* __restrict__ Bm,
             const float* __restrict__ bias, float* __restrict__ C,
             int M, int N, int K, int lda, int ldb, int ldc){
    const int NT  = (BM/TM)*(BN/TN);
    const int tid = threadIdx.x;
    const int tx  = tid % (BN/TN);
    const int ty  = tid / (BN/TN);
    const int m0  = blockIdx.y * BM;
    const int n0  = blockIdx.x * BN;
    __shared__ float As[BK][BM+1];
    __shared__ float Bs[BK][BN+1];
    float acc[TM][TN];
    #pragma unroll
    for (int a=0;a<TM;a++)
        #pragma unroll
        for (int b=0;b<TN;b++) acc[a][b] = 0.f;

    for (int kk = 0; kk < K; kk += BK){
        for (int idx = tid; idx < BM*BK; idx += NT){
            int m = idx / BK, k = idx % BK;
            int gm = m0 + m, gk = kk + k;
            As[k][m] = (gm < M && gk < K) ? A[(size_t)gm*lda + gk] : 0.f;
        }
        if (BT){
            for (int idx = tid; idx < BN*BK; idx += NT){
                int n = idx / BK, k = idx % BK;
                int gn = n0 + n, gk = kk + k;
                Bs[k][n] = (gn < N && gk < K) ? Bm[(size_t)gn*ldb + gk] : 0.f;
            }
        } else {
            for (int idx = tid; idx < BN*BK; idx += NT){
                int k = idx / BN, n = idx % BN;
                int gn = n0 + n, gk = kk + k;
                Bs[k][n] = (gn < N && gk < K) ? Bm[(size_t)gk*ldb + gn] : 0.f;
            }
        }
        __syncthreads();
        #pragma unroll
        for (int i = 0; i < BK; i++){
            float af[TM], bf[TN];
            #pragma unroll
            for (int t=0;t<TM;t++) af[t] = As[i][ty*TM+t];
            #pragma unroll
            for (int t=0;t<TN;t++) bf[t] = Bs[i][tx*TN+t];
            #pragma unroll
            for (int a=0;a<TM;a++)
                #pragma unroll
                for (int b=0;b<TN;b++) acc[a][b] += af[a]*bf[b];
        }
        __syncthreads();
    }
    #pragma unroll
    for (int a=0;a<TM;a++){
        int gm = m0 + ty*TM + a;
        if (gm >= M) continue;
        #pragma unroll
        for (int b=0;b<TN;b++){
            int gn = n0 + tx*TN + b;
            if (gn < N) C[(size_t)gm*ldc + gn] = acc[a][b] + (bias ? bias[gn] : 0.f);
        }
    }
}

// ---------------- main fused conv-GEMM + SSM epilogue ----------------------
// out[m, j] = sum_{k=0..3} sum_{dm} x[m-3+k, dm] * E[k*128+j, dm] + const[min(l,3)][j]
// then dt=softplus, dA=exp(A*dt), dBx=((1-dA)/A)*xs, written transposed [b][s][l].
#define MB 64
__global__ __launch_bounds__(256)
void main_convproj(const float* __restrict__ x, const float* __restrict__ A_log){
    const int tid = threadIdx.x;
    const int tx  = tid & 15;     // col group (j = tx*8 + tn)
    const int ty  = tid >> 4;     // row group (r = ty*4 + tm)
    const int m0  = blockIdx.x * MB;
    __shared__ float sX[(MB+3)*16];    // [67][16]  x halo tile
    __shared__ float sE[64*132];       // [k*16+i][132-pitch] E tile; reused for epilogue

    float acc[4][8];
    #pragma unroll
    for (int a=0;a<4;a++)
        #pragma unroll
        for (int b=0;b<8;b++) acc[a][b] = 0.f;

    const bool atBatchStart = ((m0 & (L_-1)) == 0);

    for (int kk = 0; kk < DMODEL; kk += 16){
        // --- load x halo tile: rows m0-3 .. m0+63 (zero across batch boundary)
        #pragma unroll
        for (int p = 0; p < 5; p++){
            int d = ty + p*16;
            if (d < MB+3){
                float v = 0.f;
                if (d >= 3 || !atBatchStart){
                    int gm = m0 - 3 + d;
                    v = x[(size_t)gm*DMODEL + kk + tx];
                }
                sX[d*16 + tx] = v;
            }
        }
        // --- load E tile: 512 rows x 16 cols
        #pragma unroll
        for (int p = 0; p < 32; p++){
            int row = ty + p*16;                  // 0..511 = k*128+j
            int k = row >> 7, j = row & 127;
            sE[(k*16 + tx)*132 + j] = g_E[(size_t)row*DMODEL + kk + tx];
        }
        __syncthreads();
        #pragma unroll
        for (int i = 0; i < 16; i++){
            float xr[7];
            #pragma unroll
            for (int d = 0; d < 7; d++) xr[d] = sX[(ty*4 + d)*16 + i];
            #pragma unroll
            for (int k = 0; k < 4; k++){
                const float* eb = &sE[(k*16 + i)*132 + tx*8];
                #pragma unroll
                for (int tn = 0; tn < 8; tn++){
                    float e = eb[tn];
                    #pragma unroll
                    for (int tm = 0; tm < 4; tm++) acc[tm][tn] += xr[tm+k]*e;
                }
            }
        }
        __syncthreads();
    }

    // --- epilogue: add consts, stage [64][128] in smem, pair (xs, dt) per state
    #pragma unroll
    for (int tm = 0; tm < 4; tm++){
        int r  = ty*4 + tm;
        int l  = (m0 + r) & (L_-1);
        int lp = l < 3 ? l : 3;
        #pragma unroll
        for (int tn = 0; tn < 8; tn++){
            int j = tx*8 + tn;
            sE[r*130 + j] = acc[tm][tn] + g_const[lp*NOUT + j];
        }
    }
    __syncthreads();
    #pragma unroll
    for (int it = 0; it < 16; it++){
        int p = tid + it*256;          // 0..4095
        int s = p >> 6;
        int r = p & 63;
        float xs = sE[r*130 + s];
        float dv = sE[r*130 + 64 + s];
        float dt = dv > 20.f ? dv : log1pf(expf(dv));
        float Aa = -expf(A_log[s]);
        float dA = expf(Aa*dt);
        float dBx = (1.f - dA)/Aa * xs;
        int m = m0 + r;
        int b = m >> 11;               // / 2048
        int l = m & (L_-1);
        size_t o = ((size_t)(b*DSTATE + s))*L_ + l;
        g_dA[o]  = dA;
        g_dBx[o] = dBx;
    }
}

// ---------------- scan: 256 independent (b,s) affine recurrences ----------
__global__ __launch_bounds__(256)
void scan_kernel(){
    const int bs = blockIdx.x;                 // b*64 + s
    const int t  = threadIdx.x;                // 0..255, 8 elems each
    const size_t base = (size_t)bs * L_;
    float a[8], bb[8];
    #pragma unroll
    for (int i=0;i<8;i++){ a[i] = g_dA[base + t*8 + i]; bb[i] = g_dBx[base + t*8 + i]; }

    // local composition (in sequence order)
    float Ai = 1.f, Bi = 0.f;
    #pragma unroll
    for (int i=0;i<8;i++){ Bi = Bi*a[i] + bb[i]; Ai *= a[i]; }

    const unsigned lane = t & 31, wid = t >> 5;
    // warp inclusive scan of affine pairs: prev(Au,Bu) then cur(Ai,Bi)
    #pragma unroll
    for (int off = 1; off < 32; off <<= 1){
        float Au = __shfl_up_sync(0xffffffffu, Ai, off);
        float Bu = __shfl_up_sync(0xffffffffu, Bi, off);
        if (lane >= off){ Bi = Ai*Bu + Bi; Ai = Ai*Au; }
    }
    __shared__ float wA[8], wB[8], pA[8], pB[8];
    if (lane == 31){ wA[wid] = Ai; wB[wid] = Bi; }
    __syncthreads();
    if (t == 0){
        float cA = 1.f, cB = 0.f;
        #pragma unroll
        for (int w = 0; w < 8; w++){
            pA[w] = cA; pB[w] = cB;
            cB = cB*wA[w] + wB[w];
            cA *= wA[w];
        }
    }
    __syncthreads();
    float eA = __shfl_up_sync(0xffffffffu, Ai, 1);
    float eB = __shfl_up_sync(0xffffffffu, Bi, 1);
    if (lane == 0){ eA = 1.f; eB = 0.f; }
    // exclusive prefix applied to z_{-1}=0: warp prefix then lane prefix
    float z = eA*pB[wid] + eB;

    int b = bs >> 6, s = bs & 63;
    float* outp = g_z + ((size_t)b*L_)*DSTATE + s;
    int l0 = t*8;
    #pragma unroll
    for (int i = 0; i < 8; i++){
        z = a[i]*z + bb[i];
        outp[(size_t)(l0 + i)*DSTATE] = z;
    }
}

// ---------------- launch ---------------------------------------------------
extern "C" void kernel_launch(void* const* d_in, const int* in_sizes, int n_in,
                              void* d_out, int out_size){
    const float* x      = (const float*)d_in[0];
    const float* W_in   = (const float*)d_in[1];
    const float* b_in   = (const float*)d_in[2];
    const float* conv_w = (const float*)d_in[3];
    const float* conv_b = (const float*)d_in[4];
    const float* W_x    = (const float*)d_in[5];
    const float* b_x    = (const float*)d_in[6];
    const float* W_dt   = (const float*)d_in[7];
    const float* b_dt   = (const float*)d_in[8];
    const float* A_log  = (const float*)d_in[9];
    const float* D_mat  = (const float*)d_in[10];
    const float* W_out  = (const float*)d_in[11];
    const float* b_out  = (const float*)d_in[12];
    float* out = (float*)d_out;

    float *pAbig, *pE, *pCt, *pZ;
    cudaGetSymbolAddress((void**)&pAbig, g_Abig);
    cudaGetSymbolAddress((void**)&pE,    g_E);
    cudaGetSymbolAddress((void**)&pCt,   g_Ct);
    cudaGetSymbolAddress((void**)&pZ,    g_z);

    prep_abig<<<1024, 256>>>(W_x, W_dt, conv_w);
    prep_const<<<dim3(NOUT, 4), 256>>>(W_x, W_dt, conv_w, conv_b, b_in, b_x, b_dt);

    // E[512,1024] = A_big[512,2048] @ W_in[2048,1024]           (NN)
    gemm_nt<64,64,16,4,4,false><<<dim3(DMODEL/64, 512/64), 256>>>(
        pAbig, W_in, nullptr, pE, 512, DMODEL, DINNER, DINNER, DMODEL, DMODEL);

    // Ct[1024,64] = W_out[1024,2048] @ D_mat[64,2048]^T          (NT)
    gemm_nt<64,64,16,4,4,true><<<dim3(DSTATE/64, DMODEL/64), 256>>>(
        W_out, D_mat, nullptr, pCt, DMODEL, DSTATE, DINNER, DINNER, DINNER, DSTATE);

    // fused conv-GEMM + SSM parameterization
    main_convproj<<<MTOT/MB, 256>>>(x, A_log);

    // 256 independent sequence scans
    scan_kernel<<<B_*DSTATE, 256>>>();

    // out[8192,1024] = z[8192,64] @ Ct[1024,64]^T + b_out        (NT)
    gemm_nt<128,128,16,8,8,true><<<dim3(DMODEL/128, MTOT/128), 256>>>(
        pZ, pCt, b_out, out, MTOT, DMODEL, DSTATE, DSTATE, DSTATE, DMODEL);
}

// round 3
// speedup vs baseline: 1.9961x; 1.9961x over previous
#include <cuda_runtime.h>
#include <math.h>

#define B_      4
#define L_      2048
#define DMODEL  1024
#define DINNER  2048
#define DSTATE  64
#define KCONV   4
#define MTOT    (B_*L_)     // 8192
#define NOUT    128         // 2*DSTATE (x_ssm | dt)
#define CTSPLIT 16

// ---------------- scratch (device globals: no allocation allowed) ----------
__device__ __align__(16) float g_ET[DMODEL*4*NOUT];  // [1024][512]  ET[dm][k*128+j]
__device__ float g_const[4*NOUT];                    // per-boundary-position bias consts
__device__ float g_Ctp[CTSPLIT*DMODEL*DSTATE];       // split-K partials
__device__ float g_Ct[DMODEL*DSTATE];                // [1024][64]  folded D_mat*W_out^T
__device__ float g_dA[B_*DSTATE*L_];                 // [b][s][l]
__device__ float g_dBx[B_*DSTATE*L_];                // [b][s][l]
__device__ float g_z[MTOT*DSTATE];                   // [m][s]

// const_l[j] = bias_P[j] + sum_c P[j,c]*(conv_b[c] + b_in[c]*sum_{k>=3-l} w[c,k])
__global__ void prep_const(const float* __restrict__ Wx, const float* __restrict__ Wdt,
                           const float* __restrict__ convw, const float* __restrict__ convb,
                           const float* __restrict__ b_in, const float* __restrict__ b_x,
                           const float* __restrict__ b_dt){
    int j  = blockIdx.x & 127;   // 0..127
    int lp = blockIdx.x >> 7;    // 0..3   (min(l,3))
    int t  = threadIdx.x;
    int kstart = 3 - lp;
    float partial = 0.f;
    for (int c = t; c < DINNER; c += 256){
        float sw = 0.f;
        #pragma unroll
        for (int k = 0; k < 4; k++) if (k >= kstart) sw += convw[c*4 + k];
        float p = (j < DSTATE) ? Wx[j*DINNER + c] : Wdt[(j-DSTATE)*DINNER + c];
        partial += p * (convb[c] + b_in[c]*sw);
    }
    __shared__ float red[256];
    red[t] = partial; __syncthreads();
    for (int s = 128; s > 0; s >>= 1){ if (t < s) red[t] += red[t+s]; __syncthreads(); }
    if (t == 0){
        float bias = (j < DSTATE) ? b_x[j] : b_dt[j-DSTATE];
        g_const[lp*NOUT + j] = red[0] + bias;
    }
}

// -------- E GEMM (fused Abig construction), stores E TRANSPOSED ------------
// ET[dm, row] = sum_c P[j,c]*convw[c,k] * W_in[c,dm],  row = k*128+j
__global__ __launch_bounds__(256)
void gemm_E(const float* __restrict__ Wx, const float* __restrict__ Wdt,
            const float* __restrict__ convw, const float* __restrict__ Win){
    const int BM=64, BN=64, BK=16, TM=4, TN=4, NT=256;
    const int tid = threadIdx.x;
    const int tx  = tid % (BN/TN);
    const int ty  = tid / (BN/TN);
    const int m0  = blockIdx.y * BM;   // row_old dim (512)
    const int n0  = blockIdx.x * BN;   // dm dim (1024)
    __shared__ float As[BK][BM+1];
    __shared__ float Bs[BK][BN+1];
    float acc[TM][TN];
    #pragma unroll
    for (int a=0;a<TM;a++)
        #pragma unroll
        for (int b=0;b<TN;b++) acc[a][b] = 0.f;

    for (int kk = 0; kk < DINNER; kk += BK){
        #pragma unroll
        for (int idx = tid; idx < BM*BK; idx += NT){
            int m = idx / BK, kq = idx % BK;
            int gm = m0 + m, gk = kk + kq;
            int k4 = gm >> 7, j = gm & 127;
            float p = (j < DSTATE) ? Wx[j*DINNER + gk] : Wdt[(j-DSTATE)*DINNER + gk];
            As[kq][m] = p * convw[gk*KCONV + k4];
        }
        #pragma unroll
        for (int idx = tid; idx < BN*BK; idx += NT){
            int kq = idx / BN, n = idx % BN;
            Bs[kq][n] = Win[(size_t)(kk+kq)*DMODEL + n0 + n];
        }
        __syncthreads();
        #pragma unroll
        for (int i = 0; i < BK; i++){
            float af[TM], bf[TN];
            #pragma unroll
            for (int t=0;t<TM;t++) af[t] = As[i][ty*TM+t];
            #pragma unroll
            for (int t=0;t<TN;t++) bf[t] = Bs[i][tx*TN+t];
            #pragma unroll
            for (int a=0;a<TM;a++)
                #pragma unroll
                for (int b=0;b<TN;b++) acc[a][b] += af[a]*bf[b];
        }
        __syncthreads();
    }
    #pragma unroll
    for (int a=0;a<TM;a++){
        int gm = m0 + ty*TM + a;
        #pragma unroll
        for (int b=0;b<TN;b++){
            int gn = n0 + tx*TN + b;
            g_ET[(size_t)gn*512 + gm] = acc[a][b];   // transposed store
        }
    }
}

// -------- Ct GEMM split-K: partials over 16 K-slices -----------------------
__global__ __launch_bounds__(256)
void gemm_ct_split(const float* __restrict__ Wout, const float* __restrict__ Dmat){
    const int BM=64, BN=64, BK=16, TM=4, TN=4, NT=256;
    const int tid = threadIdx.x;
    const int tx  = tid % (BN/TN);
    const int ty  = tid / (BN/TN);
    const int m0  = blockIdx.y * BM;
    const int z   = blockIdx.z;
    const int kbase = z * (DINNER/CTSPLIT);    // 128 per slice
    __shared__ float As[BK][BM+1];
    __shared__ float Bs[BK][BN+1];
    float acc[TM][TN];
    #pragma unroll
    for (int a=0;a<TM;a++)
        #pragma unroll
        for (int b=0;b<TN;b++) acc[a][b] = 0.f;

    for (int kk = 0; kk < DINNER/CTSPLIT; kk += BK){
        #pragma unroll
        for (int idx = tid; idx < BM*BK; idx += NT){
            int m = idx / BK, kq = idx % BK;
            As[kq][m] = Wout[(size_t)(m0+m)*DINNER + kbase + kk + kq];
        }
        #pragma unroll
        for (int idx = tid; idx < BN*BK; idx += NT){
            int n = idx / BK, kq = idx % BK;
            Bs[kq][n] = Dmat[(size_t)n*DINNER + kbase + kk + kq];
        }
        __syncthreads();
        #pragma unroll
        for (int i = 0; i < BK; i++){
            float af[TM], bf[TN];
            #pragma unroll
            for (int t=0;t<TM;t++) af[t] = As[i][ty*TM+t];
            #pragma unroll
            for (int t=0;t<TN;t++) bf[t] = Bs[i][tx*TN+t];
            #pragma unroll
            for (int a=0;a<TM;a++)
                #pragma unroll
                for (int b=0;b<TN;b++) acc[a][b] += af[a]*bf[b];
        }
        __syncthreads();
    }
    float* outp = g_Ctp + (size_t)z*DMODEL*DSTATE;
    #pragma unroll
    for (int a=0;a<TM;a++)
        #pragma unroll
        for (int b=0;b<TN;b++)
            outp[(size_t)(m0+ty*TM+a)*DSTATE + tx*TN + b] = acc[a][b];
}

__global__ void reduce_ct(){
    int i = blockIdx.x*256 + threadIdx.x;    // < 65536
    float s = 0.f;
    #pragma unroll
    for (int z = 0; z < CTSPLIT; z++) s += g_Ctp[(size_t)z*DMODEL*DSTATE + i];
    g_Ct[i] = s;
}

// ---------------- main fused conv-GEMM + SSM epilogue ----------------------
#define MB 64
__global__ __launch_bounds__(256)
void main_convproj(const float* __restrict__ x, const float* __restrict__ A_log){
    const int tid = threadIdx.x;
    const int tx  = tid & 15;     // col group (j = tx*8 + tn)
    const int ty  = tid >> 4;     // row group (r = ty*4 + tm)
    const int m0  = blockIdx.x * MB;
    __shared__ __align__(16) float sX[(MB+3)*17 + 3];   // padded pitch 17
    __shared__ __align__(16) float sE[64*132];          // [k*16+i][pitch 132]; reused for epilogue

    float acc[4][8];
    #pragma unroll
    for (int a=0;a<4;a++)
        #pragma unroll
        for (int b=0;b<8;b++) acc[a][b] = 0.f;

    const bool atBatchStart = ((m0 & (L_-1)) == 0);

    for (int kk = 0; kk < DMODEL; kk += 16){
        // --- x halo tile: rows m0-3 .. m0+63 (zero across batch boundary)
        #pragma unroll
        for (int p = 0; p < 5; p++){
            int d = ty + p*16;
            if (d < MB+3){
                float v = 0.f;
                if (d >= 3 || !atBatchStart){
                    int gm = m0 - 3 + d;
                    v = x[(size_t)gm*DMODEL + kk + tx];
                }
                sX[d*17 + tx] = v;
            }
        }
        // --- E tile from transposed ET: rows kk..kk+15, 512 cols, float4 coalesced
        #pragma unroll
        for (int p = 0; p < 8; p++){
            int idx = tid + p*256;        // 0..2047 float4s
            int fi  = idx << 2;           // float offset (0..8191)
            int i   = fi >> 9;            // /512: channel within chunk
            int col = fi & 511;           // row_old = k*128+j
            int k   = col >> 7;
            int j   = col & 127;
            float4 v = *(const float4*)&g_ET[(size_t)(kk+i)*512 + col];
            *(float4*)&sE[(k*16 + i)*132 + j] = v;
        }
        __syncthreads();
        #pragma unroll
        for (int i = 0; i < 16; i++){
            float xr[7];
            #pragma unroll
            for (int d = 0; d < 7; d++) xr[d] = sX[(ty*4 + d)*17 + i];
            #pragma unroll
            for (int k = 0; k < 4; k++){
                const float4* eb = (const float4*)&sE[(k*16 + i)*132 + tx*8];
                float4 e0 = eb[0], e1 = eb[1];
                float ev[8] = {e0.x,e0.y,e0.z,e0.w,e1.x,e1.y,e1.z,e1.w};
                #pragma unroll
                for (int tn = 0; tn < 8; tn++){
                    #pragma unroll
                    for (int tm = 0; tm < 4; tm++) acc[tm][tn] += xr[tm+k]*ev[tn];
                }
            }
        }
        __syncthreads();
    }

    // --- epilogue: add consts, stage [64][128] in smem, pair (xs, dt) per state
    #pragma unroll
    for (int tm = 0; tm < 4; tm++){
        int r  = ty*4 + tm;
        int l  = (m0 + r) & (L_-1);
        int lp = l < 3 ? l : 3;
        #pragma unroll
        for (int tn = 0; tn < 8; tn++){
            int j = tx*8 + tn;
            sE[r*130 + j] = acc[tm][tn] + g_const[lp*NOUT + j];
        }
    }
    __syncthreads();
    #pragma unroll
    for (int it = 0; it < 16; it++){
        int p = tid + it*256;          // 0..4095
        int s = p >> 6;
        int r = p & 63;
        float xs = sE[r*130 + s];
        float dv = sE[r*130 + 64 + s];
        float dt = dv > 20.f ? dv : log1pf(expf(dv));
        float Aa = -expf(A_log[s]);
        float dA = expf(Aa*dt);
        float dBx = (1.f - dA)/Aa * xs;
        int m = m0 + r;
        int b = m >> 11;
        int l = m & (L_-1);
        size_t o = ((size_t)(b*DSTATE + s))*L_ + l;
        g_dA[o]  = dA;
        g_dBx[o] = dBx;
    }
}

// ---------------- scan: 256 independent (b,s) affine recurrences ----------
__global__ __launch_bounds__(256)
void scan_kernel(){
    const int bs = blockIdx.x;
    const int t  = threadIdx.x;
    const size_t base = (size_t)bs * L_;
    float a[8], bb[8];
    #pragma unroll
    for (int i=0;i<8;i++){ a[i] = g_dA[base + t*8 + i]; bb[i] = g_dBx[base + t*8 + i]; }

    float Ai = 1.f, Bi = 0.f;
    #pragma unroll
    for (int i=0;i<8;i++){ Bi = Bi*a[i] + bb[i]; Ai *= a[i]; }

    const unsigned lane = t & 31, wid = t >> 5;
    #pragma unroll
    for (int off = 1; off < 32; off <<= 1){
        float Au = __shfl_up_sync(0xffffffffu, Ai, off);
        float Bu = __shfl_up_sync(0xffffffffu, Bi, off);
        if (lane >= off){ Bi = Ai*Bu + Bi; Ai = Ai*Au; }
    }
    __shared__ float wA[8], wB[8], pB[8];
    if (lane == 31){ wA[wid] = Ai; wB[wid] = Bi; }
    __syncthreads();
    if (t == 0){
        float cB = 0.f;
        #pragma unroll
        for (int w = 0; w < 8; w++){
            pB[w] = cB;
            cB = cB*wA[w] + wB[w];
        }
    }
    __syncthreads();
    float eA = __shfl_up_sync(0xffffffffu, Ai, 1);
    float eB = __shfl_up_sync(0xffffffffu, Bi, 1);
    if (lane == 0){ eA = 1.f; eB = 0.f; }
    float z = eA*pB[wid] + eB;

    int b = bs >> 6, s = bs & 63;
    float* outp = g_z + ((size_t)b*L_)*DSTATE + s;
    int l0 = t*8;
    #pragma unroll
    for (int i = 0; i < 8; i++){
        z = a[i]*z + bb[i];
        outp[(size_t)(l0 + i)*DSTATE] = z;
    }
}

// ---------------- final GEMM: out = z @ Ct^T + b_out -----------------------
__global__ __launch_bounds__(256)
void gemm_final(const float* __restrict__ bias, float* __restrict__ C){
    const int BM=128, BN=128, BK=16, TM=8, TN=8, NT=256;
    const int tid = threadIdx.x;
    const int tx  = tid % (BN/TN);
    const int ty  = tid / (BN/TN);
    const int m0  = blockIdx.y * BM;
    const int n0  = blockIdx.x * BN;
    __shared__ float As[BK][BM+1];
    __shared__ float Bs[BK][BN+1];
    float acc[TM][TN];
    #pragma unroll
    for (int a=0;a<TM;a++)
        #pragma unroll
        for (int b=0;b<TN;b++) acc[a][b] = 0.f;

    for (int kk = 0; kk < DSTATE; kk += BK){
        #pragma unroll
        for (int idx = tid; idx < BM*BK; idx += NT){
            int m = idx / BK, kq = idx % BK;
            As[kq][m] = g_z[(size_t)(m0+m)*DSTATE + kk + kq];
        }
        #pragma unroll
        for (int idx = tid; idx < BN*BK; idx += NT){
            int n = idx / BK, kq = idx % BK;
            Bs[kq][n] = g_Ct[(size_t)(n0+n)*DSTATE + kk + kq];
        }
        __syncthreads();
        #pragma unroll
        for (int i = 0; i < BK; i++){
            float af[TM], bf[TN];
            #pragma unroll
            for (int t=0;t<TM;t++) af[t] = As[i][ty*TM+t];
            #pragma unroll
            for (int t=0;t<TN;t++) bf[t] = Bs[i][tx*TN+t];
            #pragma unroll
            for (int a=0;a<TM;a++)
                #pragma unroll
                for (int b=0;b<TN;b++) acc[a][b] += af[a]*bf[b];
        }
        __syncthreads();
    }
    #pragma unroll
    for (int a=0;a<TM;a++){
        int gm = m0 + ty*TM + a;
        #pragma unroll
        for (int b=0;b<TN;b++){
            int gn = n0 + tx*TN + b;
            C[(size_t)gm*DMODEL + gn] = acc[a][b] + bias[gn];
        }
    }
}

// ---------------- launch ---------------------------------------------------
extern "C" void kernel_launch(void* const* d_in, const int* in_sizes, int n_in,
                              void* d_out, int out_size){
    const float* x      = (const float*)d_in[0];
    const float* W_in   = (const float*)d_in[1];
    const float* b_in   = (const float*)d_in[2];
    const float* conv_w = (const float*)d_in[3];
    const float* conv_b = (const float*)d_in[4];
    const float* W_x    = (const float*)d_in[5];
    const float* b_x    = (const float*)d_in[6];
    const float* W_dt   = (const float*)d_in[7];
    const float* b_dt   = (const float*)d_in[8];
    const float* A_log  = (const float*)d_in[9];
    const float* D_mat  = (const float*)d_in[10];
    const float* W_out  = (const float*)d_in[11];
    const float* b_out  = (const float*)d_in[12];
    float* out = (float*)d_out;

    prep_const<<<4*NOUT, 256>>>(W_x, W_dt, conv_w, conv_b, b_in, b_x, b_dt);

    // Ct partials: grid (1 n-tile, 16 m-tiles, 16 k-slices) = 256 blocks
    gemm_ct_split<<<dim3(1, DMODEL/64, CTSPLIT), 256>>>(W_out, D_mat);
    reduce_ct<<<DMODEL*DSTATE/256, 256>>>();

    // E (fused Abig) -> transposed ET
    gemm_E<<<dim3(DMODEL/64, 512/64), 256>>>(W_x, W_dt, conv_w, W_in);

    // fused conv-GEMM + SSM parameterization
    main_convproj<<<MTOT/MB, 256>>>(x, A_log);

    // 256 independent sequence scans
    scan_kernel<<<B_*DSTATE, 256>>>();

    // out[8192,1024] = z @ Ct^T + b_out
    gemm_final<<<dim3(DMODEL/128, MTOT/128), 256>>>(b_out, out);
}

// round 5
// speedup vs baseline: 3.4400x; 1.7234x over previous
#include <cuda_runtime.h>
#include <cuda_bf16.h>
#include <math.h>
#include <stdint.h>

#define B_      4
#define L_      2048
#define DMODEL  1024
#define DINNER  2048
#define DSTATE  64
#define KCONV   4
#define MTOT    (B_*L_)     // 8192
#define NOUT    128         // 2*DSTATE (x_ssm | dt)
#define CTSPLIT 16
#define ESPLIT  4
#define H4N     512         // 4*NOUT rows of Eall

// ---------------- scratch (device globals: no allocation allowed) ----------
__device__ float g_const[4*NOUT];
__device__ float g_Ctp[CTSPLIT*DMODEL*DSTATE];
__device__ float g_Ct[DMODEL*DSTATE];
__device__ float g_Ep[ESPLIT*H4N*DMODEL];                 // E split-K partials
__device__ __align__(16) __nv_bfloat16 g_Ehi[H4N*DMODEL];
__device__ __align__(16) __nv_bfloat16 g_Elo[H4N*DMODEL];
__device__ __align__(16) __nv_bfloat16 g_Xhi[(size_t)MTOT*DMODEL];
__device__ __align__(16) __nv_bfloat16 g_Xlo[(size_t)MTOT*DMODEL];
__device__ __align__(16) float g_H4[(size_t)MTOT*H4N];    // [m][k*128+j]
__device__ float g_dA[B_*DSTATE*L_];
__device__ float g_dBx[B_*DSTATE*L_];
__device__ float g_z[MTOT*DSTATE];

// ======================= helpers ===========================================
__device__ __forceinline__ uint32_t smem_u32(const void* p){
    uint32_t a;
    asm("{ .reg .u64 t; cvta.to.shared.u64 t, %1; cvt.u32.u64 %0, t; }" : "=r"(a) : "l"(p));
    return a;
}
__device__ __forceinline__ void cp16(uint32_t saddr, const void* g){
    asm volatile("cp.async.ca.shared.global [%0], [%1], 16;" :: "r"(saddr), "l"(g));
}
__device__ __forceinline__ void cp_commit(){ asm volatile("cp.async.commit_group;"); }
__device__ __forceinline__ void cp_wait0(){ asm volatile("cp.async.wait_group 0;"); }

__device__ __forceinline__ void ldsm4(uint32_t* r, uint32_t addr){
    asm volatile("ldmatrix.sync.aligned.m8n8.x4.shared.b16 {%0,%1,%2,%3}, [%4];"
        : "=r"(r[0]), "=r"(r[1]), "=r"(r[2]), "=r"(r[3]) : "r"(addr));
}
__device__ __forceinline__ void mma16816(float* d, const uint32_t* a, uint32_t b0, uint32_t b1){
    asm volatile("mma.sync.aligned.m16n8k16.row.col.f32.bf16.bf16.f32 "
        "{%0,%1,%2,%3}, {%4,%5,%6,%7}, {%8,%9}, {%0,%1,%2,%3};"
        : "+f"(d[0]), "+f"(d[1]), "+f"(d[2]), "+f"(d[3])
        : "r"(a[0]), "r"(a[1]), "r"(a[2]), "r"(a[3]), "r"(b0), "r"(b1));
}

// ======================= prep kernels ======================================
__global__ void prep_const(const float* __restrict__ Wx, const float* __restrict__ Wdt,
                           const float* __restrict__ convw, const float* __restrict__ convb,
                           const float* __restrict__ b_in, const float* __restrict__ b_x,
                           const float* __restrict__ b_dt){
    int j  = blockIdx.x & 127;
    int lp = blockIdx.x >> 7;
    int t  = threadIdx.x;
    int kstart = 3 - lp;
    float partial = 0.f;
    for (int c = t; c < DINNER; c += 256){
        float sw = 0.f;
        #pragma unroll
        for (int k = 0; k < 4; k++) if (k >= kstart) sw += convw[c*4 + k];
        float p = (j < DSTATE) ? Wx[j*DINNER + c] : Wdt[(j-DSTATE)*DINNER + c];
        partial += p * (convb[c] + b_in[c]*sw);
    }
    __shared__ float red[256];
    red[t] = partial; __syncthreads();
    for (int s = 128; s > 0; s >>= 1){ if (t < s) red[t] += red[t+s]; __syncthreads(); }
    if (t == 0){
        float bias = (j < DSTATE) ? b_x[j] : b_dt[j-DSTATE];
        g_const[lp*NOUT + j] = red[0] + bias;
    }
}

// x -> bf16 hi/lo split
__global__ void prep_xsplit(const float* __restrict__ x){
    int i = blockIdx.x*256 + threadIdx.x;        // float4 index, < MTOT*DMODEL/4
    float4 v = *(const float4*)&x[(size_t)i*4];
    __nv_bfloat16 h0 = __float2bfloat16(v.x), h1 = __float2bfloat16(v.y);
    __nv_bfloat16 h2 = __float2bfloat16(v.z), h3 = __float2bfloat16(v.w);
    __nv_bfloat16 l0 = __float2bfloat16(v.x - __bfloat162float(h0));
    __nv_bfloat16 l1 = __float2bfloat16(v.y - __bfloat162float(h1));
    __nv_bfloat16 l2 = __float2bfloat16(v.z - __bfloat162float(h2));
    __nv_bfloat16 l3 = __float2bfloat16(v.w - __bfloat162float(h3));
    __nv_bfloat162 hp0 = __halves2bfloat162(h0,h1), hp1 = __halves2bfloat162(h2,h3);
    __nv_bfloat162 lp0 = __halves2bfloat162(l0,l1), lp1 = __halves2bfloat162(l2,l3);
    uint2 hu, lu;
    hu.x = *reinterpret_cast<uint32_t*>(&hp0); hu.y = *reinterpret_cast<uint32_t*>(&hp1);
    lu.x = *reinterpret_cast<uint32_t*>(&lp0); lu.y = *reinterpret_cast<uint32_t*>(&lp1);
    *(uint2*)&g_Xhi[(size_t)i*4] = hu;
    *(uint2*)&g_Xlo[(size_t)i*4] = lu;
}

// -------- E GEMM split-K: Ep[z][row,dm] = sum_{c in slice} Abig[row,c]*Win[c,dm]
__global__ __launch_bounds__(256)
void gemm_E_split(const float* __restrict__ Wx, const float* __restrict__ Wdt,
                  const float* __restrict__ convw, const float* __restrict__ Win){
    const int BM=64, BN=64, BK=16, TM=4, TN=4, NT=256;
    const int tid = threadIdx.x;
    const int tx  = tid % (BN/TN);
    const int ty  = tid / (BN/TN);
    const int m0  = blockIdx.y * BM;
    const int n0  = blockIdx.x * BN;
    const int z   = blockIdx.z;
    const int kbase = z * (DINNER/ESPLIT);
    __shared__ float As[BK][BM+1];
    __shared__ float Bs[BK][BN+1];
    float acc[TM][TN];
    #pragma unroll
    for (int a=0;a<TM;a++)
        #pragma unroll
        for (int b=0;b<TN;b++) acc[a][b] = 0.f;

    for (int kk = 0; kk < DINNER/ESPLIT; kk += BK){
        #pragma unroll
        for (int idx = tid; idx < BM*BK; idx += NT){
            int m = idx / BK, kq = idx % BK;
            int gm = m0 + m, gk = kbase + kk + kq;
            int k4 = gm >> 7, j = gm & 127;
            float p = (j < DSTATE) ? Wx[j*DINNER + gk] : Wdt[(j-DSTATE)*DINNER + gk];
            As[kq][m] = p * convw[gk*KCONV + k4];
        }
        #pragma unroll
        for (int idx = tid; idx < BN*BK; idx += NT){
            int kq = idx / BN, n = idx % BN;
            Bs[kq][n] = Win[(size_t)(kbase+kk+kq)*DMODEL + n0 + n];
        }
        __syncthreads();
        #pragma unroll
        for (int i = 0; i < BK; i++){
            float af[TM], bf[TN];
            #pragma unroll
            for (int t=0;t<TM;t++) af[t] = As[i][ty*TM+t];
            #pragma unroll
            for (int t=0;t<TN;t++) bf[t] = Bs[i][tx*TN+t];
            #pragma unroll
            for (int a=0;a<TM;a++)
                #pragma unroll
                for (int b=0;b<TN;b++) acc[a][b] += af[a]*bf[b];
        }
        __syncthreads();
    }
    float* outp = g_Ep + (size_t)z*H4N*DMODEL;
    #pragma unroll
    for (int a=0;a<TM;a++)
        #pragma unroll
        for (int b=0;b<TN;b++)
            outp[(size_t)(m0+ty*TM+a)*DMODEL + n0+tx*TN+b] = acc[a][b];
}

__global__ void reduce_E(){
    int i = blockIdx.x*256 + threadIdx.x;     // < 512*1024
    float s = 0.f;
    #pragma unroll
    for (int z = 0; z < ESPLIT; z++) s += g_Ep[(size_t)z*H4N*DMODEL + i];
    __nv_bfloat16 hi = __float2bfloat16(s);
    __nv_bfloat16 lo = __float2bfloat16(s - __bfloat162float(hi));
    g_Ehi[i] = hi;
    g_Elo[i] = lo;
}

// -------- Ct GEMM split-K ---------------------------------------------------
__global__ __launch_bounds__(256)
void gemm_ct_split(const float* __restrict__ Wout, const float* __restrict__ Dmat){
    const int BM=64, BN=64, BK=16, TM=4, TN=4, NT=256;
    const int tid = threadIdx.x;
    const int tx  = tid % (BN/TN);
    const int ty  = tid / (BN/TN);
    const int m0  = blockIdx.y * BM;
    const int z   = blockIdx.z;
    const int kbase = z * (DINNER/CTSPLIT);
    __shared__ float As[BK][BM+1];
    __shared__ float Bs[BK][BN+1];
    float acc[TM][TN];
    #pragma unroll
    for (int a=0;a<TM;a++)
        #pragma unroll
        for (int b=0;b<TN;b++) acc[a][b] = 0.f;

    for (int kk = 0; kk < DINNER/CTSPLIT; kk += BK){
        #pragma unroll
        for (int idx = tid; idx < BM*BK; idx += NT){
            int m = idx / BK, kq = idx % BK;
            As[kq][m] = Wout[(size_t)(m0+m)*DINNER + kbase + kk + kq];
        }
        #pragma unroll
        for (int idx = tid; idx < BN*BK; idx += NT){
            int n = idx / BK, kq = idx % BK;
            Bs[kq][n] = Dmat[(size_t)n*DINNER + kbase + kk + kq];
        }
        __syncthreads();
        #pragma unroll
        for (int i = 0; i < BK; i++){
            float af[TM], bf[TN];
            #pragma unroll
            for (int t=0;t<TM;t++) af[t] = As[i][ty*TM+t];
            #pragma unroll
            for (int t=0;t<TN;t++) bf[t] = Bs[i][tx*TN+t];
            #pragma unroll
            for (int a=0;a<TM;a++)
                #pragma unroll
                for (int b=0;b<TN;b++) acc[a][b] += af[a]*bf[b];
        }
        __syncthreads();
    }
    float* outp = g_Ctp + (size_t)z*DMODEL*DSTATE;
    #pragma unroll
    for (int a=0;a<TM;a++)
        #pragma unroll
        for (int b=0;b<TN;b++)
            outp[(size_t)(m0+ty*TM+a)*DSTATE + tx*TN + b] = acc[a][b];
}

__global__ void reduce_ct(){
    int i = blockIdx.x*256 + threadIdx.x;
    float s = 0.f;
    #pragma unroll
    for (int z = 0; z < CTSPLIT; z++) s += g_Ctp[(size_t)z*DMODEL*DSTATE + i];
    g_Ct[i] = s;
}

// ======================= mma.sync H4 GEMM ==================================
// H4[8192,512] = Xsplit @ Esplit^T, bf16 hi/lo 3-pass, fp32 accum.
// BM=128, BN=128, BK=32 bf16. 8 warps: warp tile 64x32.
// SMEM rows: 32 bf16 = 64B at pitch 80B (conflict-free ldmatrix: gcd(5,8)=1).
#define H4_PITCH 80
#define H4_STG   (128*H4_PITCH)    // 10240 B per tile

__global__ __launch_bounds__(256)
void mma_h4(){
    __shared__ __align__(16) char sA[2*H4_STG];
    __shared__ __align__(16) char sB[2*H4_STG];
    const int tid  = threadIdx.x;
    const int wid  = tid >> 5, lane = tid & 31;
    const int m0   = blockIdx.x * 128;
    const int n0   = blockIdx.y * 128;
    const int wm   = (wid >> 2) * 64;     // warp row offset in tile
    const int wn   = (wid & 3) * 32;      // warp col offset in tile
    const uint32_t sAu = smem_u32(sA);
    const uint32_t sBu = smem_u32(sB);

    float acc[4][4][4];
    #pragma unroll
    for (int a=0;a<4;a++)
        #pragma unroll
        for (int b=0;b<4;b++)
            #pragma unroll
            for (int c=0;c<4;c++) acc[a][b][c] = 0.f;

    const int NIT = 3*(DMODEL/32);   // 96

    // loader lambda expressed inline: tile t -> buffer buf
    auto issue_tile = [&](int t, int buf){
        int pass = t >> 5;                 // 0:HH 1:HL 2:LH
        int kk   = (t & 31) * 32;
        const __nv_bfloat16* Ap = (pass == 2) ? g_Xlo : g_Xhi;
        const __nv_bfloat16* Bp = (pass == 1) ? g_Elo : g_Ehi;
        #pragma unroll
        for (int i = tid; i < 512; i += 256){
            int r = i >> 2, c = i & 3;
            cp16(sAu + buf*H4_STG + r*H4_PITCH + c*16,
                 Ap + (size_t)(m0 + r)*DMODEL + kk + c*8);
        }
        #pragma unroll
        for (int i = tid; i < 512; i += 256){
            int r = i >> 2, c = i & 3;
            cp16(sBu + buf*H4_STG + r*H4_PITCH + c*16,
                 Bp + (size_t)(n0 + r)*DMODEL + kk + c*8);
        }
        cp_commit();
    };

    issue_tile(0, 0);
    cp_wait0();
    __syncthreads();

    for (int t = 0; t < NIT; t++){
        int buf = t & 1;
        if (t + 1 < NIT) issue_tile(t + 1, buf ^ 1);

        // compute on buf
        #pragma unroll
        for (int ks = 0; ks < 2; ks++){
            uint32_t afr[4][4];
            #pragma unroll
            for (int mb = 0; mb < 4; mb++){
                int row = wm + mb*16 + (lane & 15);
                uint32_t addr = sAu + buf*H4_STG + row*H4_PITCH + ks*32 + (lane >> 4)*16;
                ldsm4(afr[mb], addr);
            }
            uint32_t bfr[2][4];
            #pragma unroll
            for (int nb2 = 0; nb2 < 2; nb2++){
                int row = wn + nb2*16 + ((lane >> 3) & 1)*8 + (lane & 7);
                uint32_t addr = sBu + buf*H4_STG + row*H4_PITCH + ks*32 + (lane >> 4)*16;
                ldsm4(bfr[nb2], addr);
            }
            #pragma unroll
            for (int mb = 0; mb < 4; mb++)
                #pragma unroll
                for (int nb = 0; nb < 4; nb++){
                    int nb2 = nb >> 1, odd = nb & 1;
                    uint32_t b0 = bfr[nb2][odd ? 1 : 0];
                    uint32_t b1 = bfr[nb2][odd ? 3 : 2];
                    mma16816(acc[mb][nb], afr[mb], b0, b1);
                }
        }

        if (t + 1 < NIT){ cp_wait0(); __syncthreads(); }
    }

    // epilogue: direct fp32 stores (float2 per fragment half)
    #pragma unroll
    for (int mb = 0; mb < 4; mb++){
        #pragma unroll
        for (int nb = 0; nb < 4; nb++){
            int r = m0 + wm + mb*16 + (lane >> 2);
            int c = n0 + wn + nb*8 + (lane & 3)*2;
            float2 v0 = make_float2(acc[mb][nb][0], acc[mb][nb][1]);
            float2 v1 = make_float2(acc[mb][nb][2], acc[mb][nb][3]);
            *(float2*)&g_H4[(size_t)r*H4N + c]       = v0;
            *(float2*)&g_H4[(size_t)(r+8)*H4N + c]   = v1;
        }
    }
}

// ======================= combine (shift-sum + SSM param) ===================
__global__ __launch_bounds__(256)
void combine(const float* __restrict__ A_log){
    const int tid = threadIdx.x;
    const int m0  = blockIdx.x * 64;
    __shared__ float sG[64*130];
    #pragma unroll
    for (int it = 0; it < 32; it++){
        int i = tid + it*256;          // 0..8191
        int r = i >> 7, j = i & 127;
        int m = m0 + r, l = m & (L_-1);
        int lp = l < 3 ? l : 3;
        float v = g_const[lp*NOUT + j];
        int kmin = (l >= 3) ? 0 : (3 - l);
        #pragma unroll
        for (int k = 0; k < 4; k++)
            if (k >= kmin) v += g_H4[(size_t)(m-3+k)*H4N + k*128 + j];
        sG[r*130 + j] = v;
    }
    __syncthreads();
    #pragma unroll
    for (int it = 0; it < 16; it++){
        int p = tid + it*256;          // 0..4095
        int s = p >> 6;
        int r = p & 63;
        float xs = sG[r*130 + s];
        float dv = sG[r*130 + 64 + s];
        float dt = dv > 20.f ? dv : log1pf(expf(dv));
        float Aa = -expf(A_log[s]);
        float dA = expf(Aa*dt);
        float dBx = (1.f - dA)/Aa * xs;
        int m = m0 + r;
        int b = m >> 11;
        int l = m & (L_-1);
        size_t o = ((size_t)(b*DSTATE + s))*L_ + l;
        g_dA[o]  = dA;
        g_dBx[o] = dBx;
    }
}

// ======================= scan ==============================================
__global__ __launch_bounds__(256)
void scan_kernel(){
    const int bs = blockIdx.x;
    const int t  = threadIdx.x;
    const size_t base = (size_t)bs * L_;
    float a[8], bb[8];
    #pragma unroll
    for (int i=0;i<8;i++){ a[i] = g_dA[base + t*8 + i]; bb[i] = g_dBx[base + t*8 + i]; }

    float Ai = 1.f, Bi = 0.f;
    #pragma unroll
    for (int i=0;i<8;i++){ Bi = Bi*a[i] + bb[i]; Ai *= a[i]; }

    const unsigned lane = t & 31, wid = t >> 5;
    #pragma unroll
    for (int off = 1; off < 32; off <<= 1){
        float Au = __shfl_up_sync(0xffffffffu, Ai, off);
        float Bu = __shfl_up_sync(0xffffffffu, Bi, off);
        if (lane >= off){ Bi = Ai*Bu + Bi; Ai = Ai*Au; }
    }
    __shared__ float wA[8], wB[8], pB[8];
    if (lane == 31){ wA[wid] = Ai; wB[wid] = Bi; }
    __syncthreads();
    if (t == 0){
        float cB = 0.f;
        #pragma unroll
        for (int w = 0; w < 8; w++){
            pB[w] = cB;
            cB = cB*wA[w] + wB[w];
        }
    }
    __syncthreads();
    float eA = __shfl_up_sync(0xffffffffu, Ai, 1);
    float eB = __shfl_up_sync(0xffffffffu, Bi, 1);
    if (lane == 0){ eA = 1.f; eB = 0.f; }
    float z = eA*pB[wid] + eB;

    int b = bs >> 6, s = bs & 63;
    float* outp = g_z + ((size_t)b*L_)*DSTATE + s;
    int l0 = t*8;
    #pragma unroll
    for (int i = 0; i < 8; i++){
        z = a[i]*z + bb[i];
        outp[(size_t)(l0 + i)*DSTATE] = z;
    }
}

// ======================= final GEMM ========================================
__global__ __launch_bounds__(256)
void gemm_final(const float* __restrict__ bias, float* __restrict__ C){
    const int BM=128, BN=128, BK=16, TM=8, TN=8, NT=256;
    const int tid = threadIdx.x;
    const int tx  = tid % (BN/TN);
    const int ty  = tid / (BN/TN);
    const int m0  = blockIdx.y * BM;
    const int n0  = blockIdx.x * BN;
    __shared__ float As[BK][BM+1];
    __shared__ float Bs[BK][BN+1];
    float acc[TM][TN];
    #pragma unroll
    for (int a=0;a<TM;a++)
        #pragma unroll
        for (int b=0;b<TN;b++) acc[a][b] = 0.f;

    for (int kk = 0; kk < DSTATE; kk += BK){
        #pragma unroll
        for (int idx = tid; idx < BM*BK; idx += NT){
            int m = idx / BK, kq = idx % BK;
            As[kq][m] = g_z[(size_t)(m0+m)*DSTATE + kk + kq];
        }
        #pragma unroll
        for (int idx = tid; idx < BN*BK; idx += NT){
            int n = idx / BK, kq = idx % BK;
            Bs[kq][n] = g_Ct[(size_t)(n0+n)*DSTATE + kk + kq];
        }
        __syncthreads();
        #pragma unroll
        for (int i = 0; i < BK; i++){
            float af[TM], bf[TN];
            #pragma unroll
            for (int t=0;t<TM;t++) af[t] = As[i][ty*TM+t];
            #pragma unroll
            for (int t=0;t<TN;t++) bf[t] = Bs[i][tx*TN+t];
            #pragma unroll
            for (int a=0;a<TM;a++)
                #pragma unroll
                for (int b=0;b<TN;b++) acc[a][b] += af[a]*bf[b];
        }
        __syncthreads();
    }
    #pragma unroll
    for (int a=0;a<TM;a++){
        int gm = m0 + ty*TM + a;
        #pragma unroll
        for (int b=0;b<TN;b++){
            int gn = n0 + tx*TN + b;
            C[(size_t)gm*DMODEL + gn] = acc[a][b] + bias[gn];
        }
    }
}

// ======================= launch ============================================
extern "C" void kernel_launch(void* const* d_in, const int* in_sizes, int n_in,
                              void* d_out, int out_size){
    const float* x      = (const float*)d_in[0];
    const float* W_in   = (const float*)d_in[1];
    const float* b_in   = (const float*)d_in[2];
    const float* conv_w = (const float*)d_in[3];
    const float* conv_b = (const float*)d_in[4];
    const float* W_x    = (const float*)d_in[5];
    const float* b_x    = (const float*)d_in[6];
    const float* W_dt   = (const float*)d_in[7];
    const float* b_dt   = (const float*)d_in[8];
    const float* A_log  = (const float*)d_in[9];
    const float* D_mat  = (const float*)d_in[10];
    const float* W_out  = (const float*)d_in[11];
    const float* b_out  = (const float*)d_in[12];
    float* out = (float*)d_out;

    prep_const<<<4*NOUT, 256>>>(W_x, W_dt, conv_w, conv_b, b_in, b_x, b_dt);
    prep_xsplit<<<MTOT*DMODEL/4/256, 256>>>(x);

    gemm_ct_split<<<dim3(1, DMODEL/64, CTSPLIT), 256>>>(W_out, D_mat);
    reduce_ct<<<DMODEL*DSTATE/256, 256>>>();

    gemm_E_split<<<dim3(DMODEL/64, H4N/64, ESPLIT), 256>>>(W_x, W_dt, conv_w, W_in);
    reduce_E<<<H4N*DMODEL/256, 256>>>();

    // tensor-core (mma.sync) bf16-split GEMM: H4 = X @ Eall^T
    mma_h4<<<dim3(MTOT/128, H4N/128), 256>>>();

    combine<<<MTOT/64, 256>>>(A_log);

    scan_kernel<<<B_*DSTATE, 256>>>();

    gemm_final<<<dim3(DMODEL/128, MTOT/128), 256>>>(b_out, out);
}

// round 6
// speedup vs baseline: 5.1029x; 1.4834x over previous
#include <cuda_runtime.h>
#include <cuda_bf16.h>
#include <math.h>
#include <stdint.h>

#define B_      4
#define L_      2048
#define DMODEL  1024
#define DINNER  2048
#define DSTATE  64
#define KCONV   4
#define MTOT    (B_*L_)     // 8192
#define NOUT    128         // 2*DSTATE (x_ssm | dt)
#define CTSPLIT 16
#define ESPLIT  4
#define H4N     512         // 4*NOUT rows of Eall

// ---------------- scratch (device globals: no allocation allowed) ----------
__device__ float g_const[4*NOUT];
__device__ float g_Ctp[CTSPLIT*DMODEL*DSTATE];
__device__ __align__(16) __nv_bfloat16 g_Cthi[DMODEL*DSTATE];
__device__ __align__(16) __nv_bfloat16 g_Ctlo[DMODEL*DSTATE];
__device__ float g_Ep[ESPLIT*H4N*DMODEL];                 // E split-K partials
__device__ __align__(16) __nv_bfloat16 g_Ehi[H4N*DMODEL];
__device__ __align__(16) __nv_bfloat16 g_Elo[H4N*DMODEL];
__device__ __align__(16) __nv_bfloat16 g_Abhi[H4N*DINNER];    // Abig hi/lo [512][2048]
__device__ __align__(16) __nv_bfloat16 g_Ablo[H4N*DINNER];
__device__ __align__(16) __nv_bfloat16 g_WThi[DMODEL*DINNER]; // Win^T hi/lo [1024][2048]
__device__ __align__(16) __nv_bfloat16 g_WTlo[DMODEL*DINNER];
__device__ __align__(16) __nv_bfloat16 g_Xhi[(size_t)MTOT*DMODEL];
__device__ __align__(16) __nv_bfloat16 g_Xlo[(size_t)MTOT*DMODEL];
__device__ __align__(16) __nv_bfloat16 g_zhi[MTOT*DSTATE];
__device__ __align__(16) __nv_bfloat16 g_zlo[MTOT*DSTATE];
__device__ __align__(16) float g_H4[(size_t)MTOT*H4N];    // [m][k*128+j]
__device__ float g_dA[B_*DSTATE*L_];
__device__ float g_dBx[B_*DSTATE*L_];

// ======================= helpers ===========================================
__device__ __forceinline__ uint32_t smem_u32(const void* p){
    uint32_t a;
    asm("{ .reg .u64 t; cvta.to.shared.u64 t, %1; cvt.u32.u64 %0, t; }" : "=r"(a) : "l"(p));
    return a;
}
__device__ __forceinline__ void cp16(uint32_t saddr, const void* g){
    asm volatile("cp.async.ca.shared.global [%0], [%1], 16;" :: "r"(saddr), "l"(g));
}
__device__ __forceinline__ void cp_commit(){ asm volatile("cp.async.commit_group;"); }
__device__ __forceinline__ void cp_wait0(){ asm volatile("cp.async.wait_group 0;"); }

__device__ __forceinline__ void ldsm4(uint32_t* r, uint32_t addr){
    asm volatile("ldmatrix.sync.aligned.m8n8.x4.shared.b16 {%0,%1,%2,%3}, [%4];"
        : "=r"(r[0]), "=r"(r[1]), "=r"(r[2]), "=r"(r[3]) : "r"(addr));
}
__device__ __forceinline__ void mma16816(float* d, const uint32_t* a, uint32_t b0, uint32_t b1){
    asm volatile("mma.sync.aligned.m16n8k16.row.col.f32.bf16.bf16.f32 "
        "{%0,%1,%2,%3}, {%4,%5,%6,%7}, {%8,%9}, {%0,%1,%2,%3};"
        : "+f"(d[0]), "+f"(d[1]), "+f"(d[2]), "+f"(d[3])
        : "r"(a[0]), "r"(a[1]), "r"(a[2]), "r"(a[3]), "r"(b0), "r"(b1));
}
__device__ __forceinline__ void bf_split(float v, __nv_bfloat16& h, __nv_bfloat16& l){
    h = __float2bfloat16(v);
    l = __float2bfloat16(v - __bfloat162float(h));
}

// ======================= prep kernels ======================================
__global__ void prep_const(const float* __restrict__ Wx, const float* __restrict__ Wdt,
                           const float* __restrict__ convw, const float* __restrict__ convb,
                           const float* __restrict__ b_in, const float* __restrict__ b_x,
                           const float* __restrict__ b_dt){
    int j  = blockIdx.x & 127;
    int lp = blockIdx.x >> 7;
    int t  = threadIdx.x;
    int kstart = 3 - lp;
    float partial = 0.f;
    for (int c = t; c < DINNER; c += 256){
        float sw = 0.f;
        #pragma unroll
        for (int k = 0; k < 4; k++) if (k >= kstart) sw += convw[c*4 + k];
        float p = (j < DSTATE) ? Wx[j*DINNER + c] : Wdt[(j-DSTATE)*DINNER + c];
        partial += p * (convb[c] + b_in[c]*sw);
    }
    __shared__ float red[256];
    red[t] = partial; __syncthreads();
    for (int s = 128; s > 0; s >>= 1){ if (t < s) red[t] += red[t+s]; __syncthreads(); }
    if (t == 0){
        float bias = (j < DSTATE) ? b_x[j] : b_dt[j-DSTATE];
        g_const[lp*NOUT + j] = red[0] + bias;
    }
}

__global__ void prep_xsplit(const float* __restrict__ x){
    int i = blockIdx.x*256 + threadIdx.x;        // float4 index
    float4 v = *(const float4*)&x[(size_t)i*4];
    __nv_bfloat16 h0,h1,h2,h3,l0,l1,l2,l3;
    bf_split(v.x,h0,l0); bf_split(v.y,h1,l1); bf_split(v.z,h2,l2); bf_split(v.w,h3,l3);
    __nv_bfloat162 hp0 = __halves2bfloat162(h0,h1), hp1 = __halves2bfloat162(h2,h3);
    __nv_bfloat162 lp0 = __halves2bfloat162(l0,l1), lp1 = __halves2bfloat162(l2,l3);
    uint2 hu, lu;
    hu.x = *reinterpret_cast<uint32_t*>(&hp0); hu.y = *reinterpret_cast<uint32_t*>(&hp1);
    lu.x = *reinterpret_cast<uint32_t*>(&lp0); lu.y = *reinterpret_cast<uint32_t*>(&lp1);
    *(uint2*)&g_Xhi[(size_t)i*4] = hu;
    *(uint2*)&g_Xlo[(size_t)i*4] = lu;
}

// Abig[row,c] = P[j,c]*convw[c,k4] -> bf16 hi/lo
__global__ void prep_absplit(const float* __restrict__ Wx, const float* __restrict__ Wdt,
                             const float* __restrict__ convw){
    int idx = blockIdx.x*256 + threadIdx.x;      // < 512*2048
    int c   = idx & (DINNER-1);
    int row = idx >> 11;
    int k4  = row >> 7, j = row & 127;
    float p = (j < DSTATE) ? Wx[j*DINNER + c] : Wdt[(j-DSTATE)*DINNER + c];
    float v = p * convw[c*KCONV + k4];
    __nv_bfloat16 h, l; bf_split(v, h, l);
    g_Abhi[idx] = h; g_Ablo[idx] = l;
}

// Win [c][dm] -> WinT [dm][c] bf16 hi/lo (32x32 smem transpose)
__global__ void prep_wT(const float* __restrict__ Win){
    __shared__ float t[32][33];
    int n0 = blockIdx.x*32;     // dm tile (32 tiles)
    int k0 = blockIdx.y*32;     // c tile (64 tiles)
    int tx = threadIdx.x & 31, ty = threadIdx.x >> 5;   // ty 0..7
    #pragma unroll
    for (int p = 0; p < 4; p++){
        int k = ty + p*8;
        t[k][tx] = Win[(size_t)(k0+k)*DMODEL + n0 + tx];
    }
    __syncthreads();
    #pragma unroll
    for (int p = 0; p < 4; p++){
        int n = ty + p*8;
        float v = t[tx][n];
        __nv_bfloat16 h, l; bf_split(v, h, l);
        size_t o = (size_t)(n0+n)*DINNER + k0 + tx;
        g_WThi[o] = h; g_WTlo[o] = l;
    }
}

__global__ void reduce_E(){
    int i = blockIdx.x*256 + threadIdx.x;     // < 512*1024
    float s = 0.f;
    #pragma unroll
    for (int z = 0; z < ESPLIT; z++) s += g_Ep[(size_t)z*H4N*DMODEL + i];
    __nv_bfloat16 h, l; bf_split(s, h, l);
    g_Ehi[i] = h; g_Elo[i] = l;
}

// -------- Ct GEMM split-K (SIMT, small) ------------------------------------
__global__ __launch_bounds__(256)
void gemm_ct_split(const float* __restrict__ Wout, const float* __restrict__ Dmat){
    const int BM=64, BN=64, BK=16, TM=4, TN=4, NT=256;
    const int tid = threadIdx.x;
    const int tx  = tid % (BN/TN);
    const int ty  = tid / (BN/TN);
    const int m0  = blockIdx.y * BM;
    const int z   = blockIdx.z;
    const int kbase = z * (DINNER/CTSPLIT);
    __shared__ float As[BK][BM+1];
    __shared__ float Bs[BK][BN+1];
    float acc[TM][TN];
    #pragma unroll
    for (int a=0;a<TM;a++)
        #pragma unroll
        for (int b=0;b<TN;b++) acc[a][b] = 0.f;

    for (int kk = 0; kk < DINNER/CTSPLIT; kk += BK){
        #pragma unroll
        for (int idx = tid; idx < BM*BK; idx += NT){
            int m = idx / BK, kq = idx % BK;
            As[kq][m] = Wout[(size_t)(m0+m)*DINNER + kbase + kk + kq];
        }
        #pragma unroll
        for (int idx = tid; idx < BN*BK; idx += NT){
            int n = idx / BK, kq = idx % BK;
            Bs[kq][n] = Dmat[(size_t)n*DINNER + kbase + kk + kq];
        }
        __syncthreads();
        #pragma unroll
        for (int i = 0; i < BK; i++){
            float af[TM], bf[TN];
            #pragma unroll
            for (int t=0;t<TM;t++) af[t] = As[i][ty*TM+t];
            #pragma unroll
            for (int t=0;t<TN;t++) bf[t] = Bs[i][tx*TN+t];
            #pragma unroll
            for (int a=0;a<TM;a++)
                #pragma unroll
                for (int b=0;b<TN;b++) acc[a][b] += af[a]*bf[b];
        }
        __syncthreads();
    }
    float* outp = g_Ctp + (size_t)z*DMODEL*DSTATE;
    #pragma unroll
    for (int a=0;a<TM;a++)
        #pragma unroll
        for (int b=0;b<TN;b++)
            outp[(size_t)(m0+ty*TM+a)*DSTATE + tx*TN + b] = acc[a][b];
}

__global__ void reduce_ct(){
    int i = blockIdx.x*256 + threadIdx.x;
    float s = 0.f;
    #pragma unroll
    for (int z = 0; z < CTSPLIT; z++) s += g_Ctp[(size_t)z*DMODEL*DSTATE + i];
    __nv_bfloat16 h, l; bf_split(s, h, l);
    g_Cthi[i] = h; g_Ctlo[i] = l;
}

// ======================= unified mma.sync GEMM =============================
// C[M,N] = A @ B^T, A [M,lda] k-major, B [N,ldb] n-major (row=n, cols=k).
// bf16 hi/lo 3-pass (HH, HL, LH), fp32 accum. BM=BN=128, BK=32, 8 warps 64x32.
// MODE 0: fp32 out (+bias if non-null). MODE 2: fp32 partial at C + z*sliceStride.
#define H4_PITCH 80
#define H4_STG   (128*H4_PITCH)    // 10240 B per tile

__device__ __forceinline__ void mg_issue(uint32_t sAu, uint32_t sBu, int buf,
        const __nv_bfloat16* __restrict__ Ap, const __nv_bfloat16* __restrict__ Bp,
        int m0, int n0, int lda, int ldb, int kk, int tid){
    #pragma unroll
    for (int i = tid; i < 512; i += 256){
        int r = i >> 2, c = i & 3;
        cp16(sAu + buf*H4_STG + r*H4_PITCH + c*16, Ap + (size_t)(m0 + r)*lda + kk + c*8);
    }
    #pragma unroll
    for (int i = tid; i < 512; i += 256){
        int r = i >> 2, c = i & 3;
        cp16(sBu + buf*H4_STG + r*H4_PITCH + c*16, Bp + (size_t)(n0 + r)*ldb + kk + c*8);
    }
    cp_commit();
}

template<int MODE>
__global__ __launch_bounds__(256)
void mma_gemm(const __nv_bfloat16* __restrict__ Ahi, const __nv_bfloat16* __restrict__ Alo,
              const __nv_bfloat16* __restrict__ Bhi, const __nv_bfloat16* __restrict__ Blo,
              float* __restrict__ C, const float* __restrict__ bias,
              int lda, int ldb, int kLen, int ldc, size_t sliceStride){
    __shared__ __align__(16) char sA[2*H4_STG];
    __shared__ __align__(16) char sB[2*H4_STG];
    const int tid  = threadIdx.x;
    const int wid  = tid >> 5, lane = tid & 31;
    const int m0   = blockIdx.x * 128;
    const int n0   = blockIdx.y * 128;
    const int kbase= blockIdx.z * kLen;
    const int wm   = (wid >> 2) * 64;
    const int wn   = (wid & 3) * 32;
    const uint32_t sAu = smem_u32(sA);
    const uint32_t sBu = smem_u32(sB);
    const int kt  = kLen >> 5;
    const int NIT = 3*kt;

    float acc[4][4][4];
    #pragma unroll
    for (int a=0;a<4;a++)
        #pragma unroll
        for (int b=0;b<4;b++)
            #pragma unroll
            for (int c=0;c<4;c++) acc[a][b][c] = 0.f;

    // issue tile 0
    mg_issue(sAu, sBu, 0, Ahi, Bhi, m0, n0, lda, ldb, kbase, tid);
    cp_wait0();
    __syncthreads();

    for (int t = 0; t < NIT; t++){
        int buf = t & 1;
        if (t + 1 < NIT){
            int tn2  = t + 1;
            int pass = tn2 / kt;
            int kk   = kbase + (tn2 - pass*kt)*32;
            const __nv_bfloat16* Ap = (pass == 2) ? Alo : Ahi;
            const __nv_bfloat16* Bp = (pass == 1) ? Blo : Bhi;
            mg_issue(sAu, sBu, buf ^ 1, Ap, Bp, m0, n0, lda, ldb, kk, tid);
        }

        #pragma unroll
        for (int ks = 0; ks < 2; ks++){
            uint32_t afr[4][4];
            #pragma unroll
            for (int mb = 0; mb < 4; mb++){
                int row = wm + mb*16 + (lane & 15);
                uint32_t addr = sAu + buf*H4_STG + row*H4_PITCH + ks*32 + (lane >> 4)*16;
                ldsm4(afr[mb], addr);
            }
            uint32_t bfr[2][4];
            #pragma unroll
            for (int nb2 = 0; nb2 < 2; nb2++){
                int row = wn + nb2*16 + ((lane >> 3) & 1)*8 + (lane & 7);
                uint32_t addr = sBu + buf*H4_STG + row*H4_PITCH + ks*32 + (lane >> 4)*16;
                ldsm4(bfr[nb2], addr);
            }
            #pragma unroll
            for (int mb = 0; mb < 4; mb++)
                #pragma unroll
                for (int nb = 0; nb < 4; nb++){
                    int nb2 = nb >> 1, odd = nb & 1;
                    uint32_t b0 = bfr[nb2][odd ? 1 : 0];
                    uint32_t b1 = bfr[nb2][odd ? 3 : 2];
                    mma16816(acc[mb][nb], afr[mb], b0, b1);
                }
        }

        if (t + 1 < NIT){ cp_wait0(); __syncthreads(); }
    }

    float* Co = (MODE == 2) ? (C + (size_t)blockIdx.z*sliceStride) : C;
    #pragma unroll
    for (int mb = 0; mb < 4; mb++){
        #pragma unroll
        for (int nb = 0; nb < 4; nb++){
            int r = m0 + wm + mb*16 + (lane >> 2);
            int c = n0 + wn + nb*8 + (lane & 3)*2;
            float2 v0 = make_float2(acc[mb][nb][0], acc[mb][nb][1]);
            float2 v1 = make_float2(acc[mb][nb][2], acc[mb][nb][3]);
            if (MODE == 0 && bias){
                float b0 = bias[c], b1 = bias[c+1];
                v0.x += b0; v0.y += b1;
                v1.x += b0; v1.y += b1;
            }
            *(float2*)&Co[(size_t)r*ldc + c]       = v0;
            *(float2*)&Co[(size_t)(r+8)*ldc + c]   = v1;
        }
    }
}

// ======================= combine (shift-sum + SSM param) ===================
__global__ __launch_bounds__(256)
void combine(const float* __restrict__ A_log){
    const int tid = threadIdx.x;
    const int m0  = blockIdx.x * 64;
    __shared__ float sG[64*130];
    #pragma unroll
    for (int it = 0; it < 32; it++){
        int i = tid + it*256;          // 0..8191
        int r = i >> 7, j = i & 127;
        int m = m0 + r, l = m & (L_-1);
        int lp = l < 3 ? l : 3;
        float v = g_const[lp*NOUT + j];
        int kmin = (l >= 3) ? 0 : (3 - l);
        #pragma unroll
        for (int k = 0; k < 4; k++)
            if (k >= kmin) v += g_H4[(size_t)(m-3+k)*H4N + k*128 + j];
        sG[r*130 + j] = v;
    }
    __syncthreads();
    #pragma unroll
    for (int it = 0; it < 16; it++){
        int p = tid + it*256;          // 0..4095
        int s = p >> 6;
        int r = p & 63;
        float xs = sG[r*130 + s];
        float dv = sG[r*130 + 64 + s];
        float dt = dv > 20.f ? dv : log1pf(expf(dv));
        float Aa = -expf(A_log[s]);
        float dA = expf(Aa*dt);
        float dBx = (1.f - dA)/Aa * xs;
        int m = m0 + r;
        int b = m >> 11;
        int l = m & (L_-1);
        size_t o = ((size_t)(b*DSTATE + s))*L_ + l;
        g_dA[o]  = dA;
        g_dBx[o] = dBx;
    }
}

// ======================= scan (emits z hi/lo bf16) =========================
__global__ __launch_bounds__(256)
void scan_kernel(){
    const int bs = blockIdx.x;
    const int t  = threadIdx.x;
    const size_t base = (size_t)bs * L_;
    float a[8], bb[8];
    #pragma unroll
    for (int i=0;i<8;i++){ a[i] = g_dA[base + t*8 + i]; bb[i] = g_dBx[base + t*8 + i]; }

    float Ai = 1.f, Bi = 0.f;
    #pragma unroll
    for (int i=0;i<8;i++){ Bi = Bi*a[i] + bb[i]; Ai *= a[i]; }

    const unsigned lane = t & 31, wid = t >> 5;
    #pragma unroll
    for (int off = 1; off < 32; off <<= 1){
        float Au = __shfl_up_sync(0xffffffffu, Ai, off);
        float Bu = __shfl_up_sync(0xffffffffu, Bi, off);
        if (lane >= off){ Bi = Ai*Bu + Bi; Ai = Ai*Au; }
    }
    __shared__ float wA[8], wB[8], pB[8];
    if (lane == 31){ wA[wid] = Ai; wB[wid] = Bi; }
    __syncthreads();
    if (t == 0){
        float cB = 0.f;
        #pragma unroll
        for (int w = 0; w < 8; w++){
            pB[w] = cB;
            cB = cB*wA[w] + wB[w];
        }
    }
    __syncthreads();
    float eA = __shfl_up_sync(0xffffffffu, Ai, 1);
    float eB = __shfl_up_sync(0xffffffffu, Bi, 1);
    if (lane == 0){ eA = 1.f; eB = 0.f; }
    float z = eA*pB[wid] + eB;

    int b = bs >> 6, s = bs & 63;
    size_t obase = (size_t)b*L_*DSTATE + s;
    int l0 = t*8;
    #pragma unroll
    for (int i = 0; i < 8; i++){
        z = a[i]*z + bb[i];
        __nv_bfloat16 h, l; bf_split(z, h, l);
        size_t o = obase + (size_t)(l0 + i)*DSTATE;
        g_zhi[o] = h;
        g_zlo[o] = l;
    }
}

// ======================= launch ============================================
extern "C" void kernel_launch(void* const* d_in, const int* in_sizes, int n_in,
                              void* d_out, int out_size){
    const float* x      = (const float*)d_in[0];
    const float* W_in   = (const float*)d_in[1];
    const float* b_in   = (const float*)d_in[2];
    const float* conv_w = (const float*)d_in[3];
    const float* conv_b = (const float*)d_in[4];
    const float* W_x    = (const float*)d_in[5];
    const float* b_x    = (const float*)d_in[6];
    const float* W_dt   = (const float*)d_in[7];
    const float* b_dt   = (const float*)d_in[8];
    const float* A_log  = (const float*)d_in[9];
    const float* D_mat  = (const float*)d_in[10];
    const float* W_out  = (const float*)d_in[11];
    const float* b_out  = (const float*)d_in[12];
    float* out = (float*)d_out;

    float *pEp, *pH4, *pOut = out;
    cudaGetSymbolAddress((void**)&pEp, g_Ep);
    cudaGetSymbolAddress((void**)&pH4, g_H4);
    __nv_bfloat16 *pAbh, *pAbl, *pWTh, *pWTl, *pEh, *pEl, *pXh, *pXl, *pZh, *pZl, *pCth, *pCtl;
    cudaGetSymbolAddress((void**)&pAbh, g_Abhi);
    cudaGetSymbolAddress((void**)&pAbl, g_Ablo);
    cudaGetSymbolAddress((void**)&pWTh, g_WThi);
    cudaGetSymbolAddress((void**)&pWTl, g_WTlo);
    cudaGetSymbolAddress((void**)&pEh,  g_Ehi);
    cudaGetSymbolAddress((void**)&pEl,  g_Elo);
    cudaGetSymbolAddress((void**)&pXh,  g_Xhi);
    cudaGetSymbolAddress((void**)&pXl,  g_Xlo);
    cudaGetSymbolAddress((void**)&pZh,  g_zhi);
    cudaGetSymbolAddress((void**)&pZl,  g_zlo);
    cudaGetSymbolAddress((void**)&pCth, g_Cthi);
    cudaGetSymbolAddress((void**)&pCtl, g_Ctlo);

    prep_const<<<4*NOUT, 256>>>(W_x, W_dt, conv_w, conv_b, b_in, b_x, b_dt);
    prep_xsplit<<<MTOT*DMODEL/4/256, 256>>>(x);
    prep_absplit<<<H4N*DINNER/256, 256>>>(W_x, W_dt, conv_w);
    prep_wT<<<dim3(DMODEL/32, DINNER/32), 256>>>(W_in);

    gemm_ct_split<<<dim3(1, DMODEL/64, CTSPLIT), 256>>>(W_out, D_mat);
    reduce_ct<<<DMODEL*DSTATE/256, 256>>>();

    // E = Abig @ Win  (tensor cores, split-K=4): partials -> reduce to hi/lo
    mma_gemm<2><<<dim3(H4N/128, DMODEL/128, ESPLIT), 256>>>(
        pAbh, pAbl, pWTh, pWTl, pEp, nullptr,
        DINNER, DINNER, DINNER/ESPLIT, DMODEL, (size_t)H4N*DMODEL);
    reduce_E<<<H4N*DMODEL/256, 256>>>();

    // H4 = X @ Eall^T (tensor cores)
    mma_gemm<0><<<dim3(MTOT/128, H4N/128, 1), 256>>>(
        pXh, pXl, pEh, pEl, pH4, nullptr,
        DMODEL, DMODEL, DMODEL, H4N, 0);

    combine<<<MTOT/64, 256>>>(A_log);

    scan_kernel<<<B_*DSTATE, 256>>>();

    // out = z @ Ct^T + b_out (tensor cores)
    mma_gemm<0><<<dim3(MTOT/128, DMODEL/128, 1), 256>>>(
        pZh, pZl, pCth, pCtl, pOut, b_out,
        DSTATE, DSTATE, DSTATE, DMODEL, 0);
}

// round 7
// speedup vs baseline: 5.6757x; 1.1123x over previous
#include <cuda_runtime.h>
#include <cuda_bf16.h>
#include <math.h>
#include <stdint.h>

#define B_      4
#define L_      2048
#define DMODEL  1024
#define DINNER  2048
#define DSTATE  64
#define KCONV   4
#define MTOT    (B_*L_)     // 8192
#define NOUT    128         // 2*DSTATE (x_ssm | dt)
#define CTSPLIT 16
#define ESPLIT  4
#define H4N     512         // 4*NOUT rows of Eall

// ---------------- scratch (device globals: no allocation allowed) ----------
__device__ float g_const[4*NOUT];
__device__ float g_Ctp[CTSPLIT*DMODEL*DSTATE];
__device__ __align__(16) __nv_bfloat16 g_Cthi[DMODEL*DSTATE];
__device__ __align__(16) __nv_bfloat16 g_Ctlo[DMODEL*DSTATE];
__device__ float g_Ep[ESPLIT*H4N*DMODEL];                 // E split-K partials
__device__ __align__(16) __nv_bfloat16 g_Ehi[H4N*DMODEL];
__device__ __align__(16) __nv_bfloat16 g_Elo[H4N*DMODEL];
__device__ __align__(16) __nv_bfloat16 g_Abhi[H4N*DINNER];
__device__ __align__(16) __nv_bfloat16 g_Ablo[H4N*DINNER];
__device__ __align__(16) __nv_bfloat16 g_WThi[DMODEL*DINNER];
__device__ __align__(16) __nv_bfloat16 g_WTlo[DMODEL*DINNER];
__device__ __align__(16) __nv_bfloat16 g_Xhi[(size_t)MTOT*DMODEL];
__device__ __align__(16) __nv_bfloat16 g_Xlo[(size_t)MTOT*DMODEL];
__device__ __align__(16) __nv_bfloat16 g_zThi[B_*DSTATE*L_];   // [b*64+s][l]
__device__ __align__(16) __nv_bfloat16 g_zTlo[B_*DSTATE*L_];
__device__ __align__(16) __nv_bfloat16 g_zhi[MTOT*DSTATE];     // [m][s]
__device__ __align__(16) __nv_bfloat16 g_zlo[MTOT*DSTATE];
__device__ __align__(16) float g_H4[(size_t)MTOT*H4N];         // [m][k*128+j]
__device__ float g_dA[B_*DSTATE*L_];
__device__ float g_dBx[B_*DSTATE*L_];

// ======================= helpers ===========================================
__device__ __forceinline__ uint32_t smem_u32(const void* p){
    uint32_t a;
    asm("{ .reg .u64 t; cvta.to.shared.u64 t, %1; cvt.u32.u64 %0, t; }" : "=r"(a) : "l"(p));
    return a;
}
__device__ __forceinline__ void cp16(uint32_t saddr, const void* g){
    asm volatile("cp.async.ca.shared.global [%0], [%1], 16;" :: "r"(saddr), "l"(g));
}
__device__ __forceinline__ void cp_commit(){ asm volatile("cp.async.commit_group;"); }
__device__ __forceinline__ void cp_wait0(){ asm volatile("cp.async.wait_group 0;"); }

__device__ __forceinline__ void ldsm4(uint32_t* r, uint32_t addr){
    asm volatile("ldmatrix.sync.aligned.m8n8.x4.shared.b16 {%0,%1,%2,%3}, [%4];"
        : "=r"(r[0]), "=r"(r[1]), "=r"(r[2]), "=r"(r[3]) : "r"(addr));
}
__device__ __forceinline__ void mma16816(float* d, const uint32_t* a, uint32_t b0, uint32_t b1){
    asm volatile("mma.sync.aligned.m16n8k16.row.col.f32.bf16.bf16.f32 "
        "{%0,%1,%2,%3}, {%4,%5,%6,%7}, {%8,%9}, {%0,%1,%2,%3};"
        : "+f"(d[0]), "+f"(d[1]), "+f"(d[2]), "+f"(d[3])
        : "r"(a[0]), "r"(a[1]), "r"(a[2]), "r"(a[3]), "r"(b0), "r"(b1));
}
__device__ __forceinline__ void bf_split(float v, __nv_bfloat16& h, __nv_bfloat16& l){
    h = __float2bfloat16(v);
    l = __float2bfloat16(v - __bfloat162float(h));
}

// ======================= prep kernels ======================================
__global__ void prep_const(const float* __restrict__ Wx, const float* __restrict__ Wdt,
                           const float* __restrict__ convw, const float* __restrict__ convb,
                           const float* __restrict__ b_in, const float* __restrict__ b_x,
                           const float* __restrict__ b_dt){
    int j  = blockIdx.x & 127;
    int lp = blockIdx.x >> 7;
    int t  = threadIdx.x;
    int kstart = 3 - lp;
    float partial = 0.f;
    for (int c = t; c < DINNER; c += 256){
        float sw = 0.f;
        #pragma unroll
        for (int k = 0; k < 4; k++) if (k >= kstart) sw += convw[c*4 + k];
        float p = (j < DSTATE) ? Wx[j*DINNER + c] : Wdt[(j-DSTATE)*DINNER + c];
        partial += p * (convb[c] + b_in[c]*sw);
    }
    __shared__ float red[256];
    red[t] = partial; __syncthreads();
    for (int s = 128; s > 0; s >>= 1){ if (t < s) red[t] += red[t+s]; __syncthreads(); }
    if (t == 0){
        float bias = (j < DSTATE) ? b_x[j] : b_dt[j-DSTATE];
        g_const[lp*NOUT + j] = red[0] + bias;
    }
}

__global__ void prep_xsplit(const float* __restrict__ x){
    int i = blockIdx.x*256 + threadIdx.x;        // float4 index
    float4 v = *(const float4*)&x[(size_t)i*4];
    __nv_bfloat16 h0,h1,h2,h3,l0,l1,l2,l3;
    bf_split(v.x,h0,l0); bf_split(v.y,h1,l1); bf_split(v.z,h2,l2); bf_split(v.w,h3,l3);
    __nv_bfloat162 hp0 = __halves2bfloat162(h0,h1), hp1 = __halves2bfloat162(h2,h3);
    __nv_bfloat162 lp0 = __halves2bfloat162(l0,l1), lp1 = __halves2bfloat162(l2,l3);
    uint2 hu, lu;
    hu.x = *reinterpret_cast<uint32_t*>(&hp0); hu.y = *reinterpret_cast<uint32_t*>(&hp1);
    lu.x = *reinterpret_cast<uint32_t*>(&lp0); lu.y = *reinterpret_cast<uint32_t*>(&lp1);
    *(uint2*)&g_Xhi[(size_t)i*4] = hu;
    *(uint2*)&g_Xlo[(size_t)i*4] = lu;
}

__global__ void prep_absplit(const float* __restrict__ Wx, const float* __restrict__ Wdt,
                             const float* __restrict__ convw){
    int idx = blockIdx.x*256 + threadIdx.x;      // < 512*2048
    int c   = idx & (DINNER-1);
    int row = idx >> 11;
    int k4  = row >> 7, j = row & 127;
    float p = (j < DSTATE) ? Wx[j*DINNER + c] : Wdt[(j-DSTATE)*DINNER + c];
    float v = p * convw[c*KCONV + k4];
    __nv_bfloat16 h, l; bf_split(v, h, l);
    g_Abhi[idx] = h; g_Ablo[idx] = l;
}

__global__ void prep_wT(const float* __restrict__ Win){
    __shared__ float t[32][33];
    int n0 = blockIdx.x*32;
    int k0 = blockIdx.y*32;
    int tx = threadIdx.x & 31, ty = threadIdx.x >> 5;
    #pragma unroll
    for (int p = 0; p < 4; p++){
        int k = ty + p*8;
        t[k][tx] = Win[(size_t)(k0+k)*DMODEL + n0 + tx];
    }
    __syncthreads();
    #pragma unroll
    for (int p = 0; p < 4; p++){
        int n = ty + p*8;
        float v = t[tx][n];
        __nv_bfloat16 h, l; bf_split(v, h, l);
        size_t o = (size_t)(n0+n)*DINNER + k0 + tx;
        g_WThi[o] = h; g_WTlo[o] = l;
    }
}

__global__ void reduce_E(){
    int i = blockIdx.x*256 + threadIdx.x;
    float s = 0.f;
    #pragma unroll
    for (int z = 0; z < ESPLIT; z++) s += g_Ep[(size_t)z*H4N*DMODEL + i];
    __nv_bfloat16 h, l; bf_split(s, h, l);
    g_Ehi[i] = h; g_Elo[i] = l;
}

// -------- Ct GEMM split-K (SIMT, small) ------------------------------------
__global__ __launch_bounds__(256)
void gemm_ct_split(const float* __restrict__ Wout, const float* __restrict__ Dmat){
    const int BM=64, BN=64, BK=16, TM=4, TN=4, NT=256;
    const int tid = threadIdx.x;
    const int tx  = tid % (BN/TN);
    const int ty  = tid / (BN/TN);
    const int m0  = blockIdx.y * BM;
    const int z   = blockIdx.z;
    const int kbase = z * (DINNER/CTSPLIT);
    __shared__ float As[BK][BM+1];
    __shared__ float Bs[BK][BN+1];
    float acc[TM][TN];
    #pragma unroll
    for (int a=0;a<TM;a++)
        #pragma unroll
        for (int b=0;b<TN;b++) acc[a][b] = 0.f;

    for (int kk = 0; kk < DINNER/CTSPLIT; kk += BK){
        #pragma unroll
        for (int idx = tid; idx < BM*BK; idx += NT){
            int m = idx / BK, kq = idx % BK;
            As[kq][m] = Wout[(size_t)(m0+m)*DINNER + kbase + kk + kq];
        }
        #pragma unroll
        for (int idx = tid; idx < BN*BK; idx += NT){
            int n = idx / BK, kq = idx % BK;
            Bs[kq][n] = Dmat[(size_t)n*DINNER + kbase + kk + kq];
        }
        __syncthreads();
        #pragma unroll
        for (int i = 0; i < BK; i++){
            float af[TM], bf[TN];
            #pragma unroll
            for (int t=0;t<TM;t++) af[t] = As[i][ty*TM+t];
            #pragma unroll
            for (int t=0;t<TN;t++) bf[t] = Bs[i][tx*TN+t];
            #pragma unroll
            for (int a=0;a<TM;a++)
                #pragma unroll
                for (int b=0;b<TN;b++) acc[a][b] += af[a]*bf[b];
        }
        __syncthreads();
    }
    float* outp = g_Ctp + (size_t)z*DMODEL*DSTATE;
    #pragma unroll
    for (int a=0;a<TM;a++)
        #pragma unroll
        for (int b=0;b<TN;b++)
            outp[(size_t)(m0+ty*TM+a)*DSTATE + tx*TN + b] = acc[a][b];
}

__global__ void reduce_ct(){
    int i = blockIdx.x*256 + threadIdx.x;
    float s = 0.f;
    #pragma unroll
    for (int z = 0; z < CTSPLIT; z++) s += g_Ctp[(size_t)z*DMODEL*DSTATE + i];
    __nv_bfloat16 h, l; bf_split(s, h, l);
    g_Cthi[i] = h; g_Ctlo[i] = l;
}

// ======================= unified fused-pass mma.sync GEMM ==================
// C = A @ B^T with bf16 hi/lo error compensation in ONE K-sweep:
// per K-tile load {Ah, Al, Bh, Bl} once, run 3 MMA groups (AhBh, AhBl, AlBh).
// BM=BN=128, BK=32, 8 warps (64x32 each). Dynamic smem 80KB (double buffer).
#define MG_PITCH 80
#define MG_TILE  (128*MG_PITCH)       // 10240 B
#define MG_STG   (4*MG_TILE)          // 40960 B per stage
#define MG_SMEM  (2*MG_STG)           // 81920 B

__device__ __forceinline__ void mg_issue4(uint32_t base,
        const __nv_bfloat16* __restrict__ Ah, const __nv_bfloat16* __restrict__ Al,
        const __nv_bfloat16* __restrict__ Bh, const __nv_bfloat16* __restrict__ Bl,
        int m0, int n0, int lda, int ldb, int kk, int tid){
    #pragma unroll
    for (int i = tid; i < 512; i += 256){
        int r = i >> 2, c = i & 3;
        uint32_t o = r*MG_PITCH + c*16;
        size_t ga = (size_t)(m0 + r)*lda + kk + c*8;
        size_t gb = (size_t)(n0 + r)*ldb + kk + c*8;
        cp16(base +             o, Ah + ga);
        cp16(base + MG_TILE   + o, Al + ga);
        cp16(base + 2*MG_TILE + o, Bh + gb);
        cp16(base + 3*MG_TILE + o, Bl + gb);
    }
    cp_commit();
}

template<int MODE>
__global__ __launch_bounds__(256)
void mma_gemm(const __nv_bfloat16* __restrict__ Ahi, const __nv_bfloat16* __restrict__ Alo,
              const __nv_bfloat16* __restrict__ Bhi, const __nv_bfloat16* __restrict__ Blo,
              float* __restrict__ C, const float* __restrict__ bias,
              int lda, int ldb, int kLen, int ldc, size_t sliceStride){
    extern __shared__ __align__(16) char dsm[];
    const int tid  = threadIdx.x;
    const int wid  = tid >> 5, lane = tid & 31;
    const int m0   = blockIdx.x * 128;
    const int n0   = blockIdx.y * 128;
    const int kbase= blockIdx.z * kLen;
    const int wm   = (wid >> 2) * 64;
    const int wn   = (wid & 3) * 32;
    const uint32_t sbu = smem_u32(dsm);
    const int NIT = kLen >> 5;

    float acc[4][4][4];
    #pragma unroll
    for (int a=0;a<4;a++)
        #pragma unroll
        for (int b=0;b<4;b++)
            #pragma unroll
            for (int c=0;c<4;c++) acc[a][b][c] = 0.f;

    mg_issue4(sbu, Ahi, Alo, Bhi, Blo, m0, n0, lda, ldb, kbase, tid);
    cp_wait0();
    __syncthreads();

    for (int t = 0; t < NIT; t++){
        int buf = t & 1;
        if (t + 1 < NIT)
            mg_issue4(sbu + (buf^1)*MG_STG, Ahi, Alo, Bhi, Blo,
                      m0, n0, lda, ldb, kbase + (t+1)*32, tid);

        const uint32_t sb = sbu + buf*MG_STG;
        #pragma unroll
        for (int ks = 0; ks < 2; ks++){
            uint32_t ah[4][4], al[4][4], bh[2][4], bl[2][4];
            #pragma unroll
            for (int mb = 0; mb < 4; mb++){
                int row = wm + mb*16 + (lane & 15);
                uint32_t o = row*MG_PITCH + ks*32 + (lane >> 4)*16;
                ldsm4(ah[mb], sb + o);
                ldsm4(al[mb], sb + MG_TILE + o);
            }
            #pragma unroll
            for (int nb2 = 0; nb2 < 2; nb2++){
                int row = wn + nb2*16 + ((lane >> 3) & 1)*8 + (lane & 7);
                uint32_t o = row*MG_PITCH + ks*32 + (lane >> 4)*16;
                ldsm4(bh[nb2], sb + 2*MG_TILE + o);
                ldsm4(bl[nb2], sb + 3*MG_TILE + o);
            }
            #pragma unroll
            for (int mb = 0; mb < 4; mb++)
                #pragma unroll
                for (int nb = 0; nb < 4; nb++){
                    int nb2 = nb >> 1, odd = nb & 1;
                    mma16816(acc[mb][nb], ah[mb], bh[nb2][odd?1:0], bh[nb2][odd?3:2]);
                }
            #pragma unroll
            for (int mb = 0; mb < 4; mb++)
                #pragma unroll
                for (int nb = 0; nb < 4; nb++){
                    int nb2 = nb >> 1, odd = nb & 1;
                    mma16816(acc[mb][nb], ah[mb], bl[nb2][odd?1:0], bl[nb2][odd?3:2]);
                }
            #pragma unroll
            for (int mb = 0; mb < 4; mb++)
                #pragma unroll
                for (int nb = 0; nb < 4; nb++){
                    int nb2 = nb >> 1, odd = nb & 1;
                    mma16816(acc[mb][nb], al[mb], bh[nb2][odd?1:0], bh[nb2][odd?3:2]);
                }
        }

        if (t + 1 < NIT){ cp_wait0(); __syncthreads(); }
    }

    float* Co = (MODE == 2) ? (C + (size_t)blockIdx.z*sliceStride) : C;
    #pragma unroll
    for (int mb = 0; mb < 4; mb++){
        #pragma unroll
        for (int nb = 0; nb < 4; nb++){
            int r = m0 + wm + mb*16 + (lane >> 2);
            int c = n0 + wn + nb*8 + (lane & 3)*2;
            float2 v0 = make_float2(acc[mb][nb][0], acc[mb][nb][1]);
            float2 v1 = make_float2(acc[mb][nb][2], acc[mb][nb][3]);
            if (MODE == 0 && bias){
                float b0 = bias[c], b1 = bias[c+1];
                v0.x += b0; v0.y += b1;
                v1.x += b0; v1.y += b1;
            }
            *(float2*)&Co[(size_t)r*ldc + c]       = v0;
            *(float2*)&Co[(size_t)(r+8)*ldc + c]   = v1;
        }
    }
}

// ======================= combine (shift-sum + SSM param) ===================
__global__ __launch_bounds__(256)
void combine(const float* __restrict__ A_log){
    const int tid = threadIdx.x;
    const int m0  = blockIdx.x * 64;
    __shared__ float sG[64*130];
    #pragma unroll
    for (int it = 0; it < 32; it++){
        int i = tid + it*256;
        int r = i >> 7, j = i & 127;
        int m = m0 + r, l = m & (L_-1);
        int lp = l < 3 ? l : 3;
        float v = g_const[lp*NOUT + j];
        int kmin = (l >= 3) ? 0 : (3 - l);
        #pragma unroll
        for (int k = 0; k < 4; k++)
            if (k >= kmin) v += g_H4[(size_t)(m-3+k)*H4N + k*128 + j];
        sG[r*130 + j] = v;
    }
    __syncthreads();
    #pragma unroll
    for (int it = 0; it < 16; it++){
        int p = tid + it*256;
        int s = p >> 6;
        int r = p & 63;
        float xs = sG[r*130 + s];
        float dv = sG[r*130 + 64 + s];
        float dt = dv > 20.f ? dv : log1pf(expf(dv));
        float Aa = -expf(A_log[s]);
        float dA = expf(Aa*dt);
        float dBx = (1.f - dA)/Aa * xs;
        int m = m0 + r;
        int b = m >> 11;
        int l = m & (L_-1);
        size_t o = ((size_t)(b*DSTATE + s))*L_ + l;
        g_dA[o]  = dA;
        g_dBx[o] = dBx;
    }
}

// ======================= scan (coalesced zT output) ========================
__global__ __launch_bounds__(256)
void scan_kernel(){
    const int bs = blockIdx.x;
    const int t  = threadIdx.x;
    const size_t base = (size_t)bs * L_;
    float a[8], bb[8];
    #pragma unroll
    for (int i=0;i<8;i++){ a[i] = g_dA[base + t*8 + i]; bb[i] = g_dBx[base + t*8 + i]; }

    float Ai = 1.f, Bi = 0.f;
    #pragma unroll
    for (int i=0;i<8;i++){ Bi = Bi*a[i] + bb[i]; Ai *= a[i]; }

    const unsigned lane = t & 31, wid = t >> 5;
    #pragma unroll
    for (int off = 1; off < 32; off <<= 1){
        float Au = __shfl_up_sync(0xffffffffu, Ai, off);
        float Bu = __shfl_up_sync(0xffffffffu, Bi, off);
        if (lane >= off){ Bi = Ai*Bu + Bi; Ai = Ai*Au; }
    }
    __shared__ float wA[8], wB[8], pB[8];
    if (lane == 31){ wA[wid] = Ai; wB[wid] = Bi; }
    __syncthreads();
    if (t == 0){
        float cB = 0.f;
        #pragma unroll
        for (int w = 0; w < 8; w++){
            pB[w] = cB;
            cB = cB*wA[w] + wB[w];
        }
    }
    __syncthreads();
    float eA = __shfl_up_sync(0xffffffffu, Ai, 1);
    float eB = __shfl_up_sync(0xffffffffu, Bi, 1);
    if (lane == 0){ eA = 1.f; eB = 0.f; }
    float z = eA*pB[wid] + eB;

    __nv_bfloat16 hb[8], lb[8];
    #pragma unroll
    for (int i = 0; i < 8; i++){
        z = a[i]*z + bb[i];
        bf_split(z, hb[i], lb[i]);
    }
    *(uint4*)&g_zThi[base + t*8] = *(uint4*)hb;
    *(uint4*)&g_zTlo[base + t*8] = *(uint4*)lb;
}

// zT [b*64+s][l] -> z [m][s] (64x64 smem tiles, hi+lo)
__global__ __launch_bounds__(256)
void transpose_z(){
    __shared__ __nv_bfloat16 th[64][66];
    __shared__ __nv_bfloat16 tl[64][66];
    const int tid = threadIdx.x;
    const int l0  = blockIdx.x * 64;
    const int b   = blockIdx.y;
    #pragma unroll
    for (int it = 0; it < 16; it++){
        int i = tid + it*256;
        int s = i >> 6, lo = i & 63;
        size_t o = (size_t)(b*DSTATE + s)*L_ + l0 + lo;
        th[s][lo] = g_zThi[o];
        tl[s][lo] = g_zTlo[o];
    }
    __syncthreads();
    #pragma unroll
    for (int it = 0; it < 16; it++){
        int i = tid + it*256;
        int l = i >> 6, s = i & 63;
        size_t o = (size_t)(b*L_ + l0 + l)*DSTATE + s;
        g_zhi[o] = th[s][l];
        g_zlo[o] = tl[s][l];
    }
}

// ======================= launch ============================================
extern "C" void kernel_launch(void* const* d_in, const int* in_sizes, int n_in,
                              void* d_out, int out_size){
    const float* x      = (const float*)d_in[0];
    const float* W_in   = (const float*)d_in[1];
    const float* b_in   = (const float*)d_in[2];
    const float* conv_w = (const float*)d_in[3];
    const float* conv_b = (const float*)d_in[4];
    const float* W_x    = (const float*)d_in[5];
    const float* b_x    = (const float*)d_in[6];
    const float* W_dt   = (const float*)d_in[7];
    const float* b_dt   = (const float*)d_in[8];
    const float* A_log  = (const float*)d_in[9];
    const float* D_mat  = (const float*)d_in[10];
    const float* W_out  = (const float*)d_in[11];
    const float* b_out  = (const float*)d_in[12];
    float* out = (float*)d_out;

    cudaFuncSetAttribute(mma_gemm<0>, cudaFuncAttributeMaxDynamicSharedMemorySize, MG_SMEM);
    cudaFuncSetAttribute(mma_gemm<2>, cudaFuncAttributeMaxDynamicSharedMemorySize, MG_SMEM);

    float *pEp, *pH4;
    cudaGetSymbolAddress((void**)&pEp, g_Ep);
    cudaGetSymbolAddress((void**)&pH4, g_H4);
    __nv_bfloat16 *pAbh, *pAbl, *pWTh, *pWTl, *pEh, *pEl, *pXh, *pXl, *pZh, *pZl, *pCth, *pCtl;
    cudaGetSymbolAddress((void**)&pAbh, g_Abhi);
    cudaGetSymbolAddress((void**)&pAbl, g_Ablo);
    cudaGetSymbolAddress((void**)&pWTh, g_WThi);
    cudaGetSymbolAddress((void**)&pWTl, g_WTlo);
    cudaGetSymbolAddress((void**)&pEh,  g_Ehi);
    cudaGetSymbolAddress((void**)&pEl,  g_Elo);
    cudaGetSymbolAddress((void**)&pXh,  g_Xhi);
    cudaGetSymbolAddress((void**)&pXl,  g_Xlo);
    cudaGetSymbolAddress((void**)&pZh,  g_zhi);
    cudaGetSymbolAddress((void**)&pZl,  g_zlo);
    cudaGetSymbolAddress((void**)&pCth, g_Cthi);
    cudaGetSymbolAddress((void**)&pCtl, g_Ctlo);

    prep_const<<<4*NOUT, 256>>>(W_x, W_dt, conv_w, conv_b, b_in, b_x, b_dt);
    prep_xsplit<<<MTOT*DMODEL/4/256, 256>>>(x);
    prep_absplit<<<H4N*DINNER/256, 256>>>(W_x, W_dt, conv_w);
    prep_wT<<<dim3(DMODEL/32, DINNER/32), 256>>>(W_in);

    gemm_ct_split<<<dim3(1, DMODEL/64, CTSPLIT), 256>>>(W_out, D_mat);
    reduce_ct<<<DMODEL*DSTATE/256, 256>>>();

    // E = Abig @ Win (fused-pass mma, split-K=4)
    mma_gemm<2><<<dim3(H4N/128, DMODEL/128, ESPLIT), 256, MG_SMEM>>>(
        pAbh, pAbl, pWTh, pWTl, pEp, nullptr,
        DINNER, DINNER, DINNER/ESPLIT, DMODEL, (size_t)H4N*DMODEL);
    reduce_E<<<H4N*DMODEL/256, 256>>>();

    // H4 = X @ Eall^T (fused-pass mma)
    mma_gemm<0><<<dim3(MTOT/128, H4N/128, 1), 256, MG_SMEM>>>(
        pXh, pXl, pEh, pEl, pH4, nullptr,
        DMODEL, DMODEL, DMODEL, H4N, 0);

    combine<<<MTOT/64, 256>>>(A_log);

    scan_kernel<<<B_*DSTATE, 256>>>();
    transpose_z<<<dim3(L_/64, B_), 256>>>();

    // out = z @ Ct^T + b_out (fused-pass mma)
    mma_gemm<0><<<dim3(MTOT/128, DMODEL/128, 1), 256, MG_SMEM>>>(
        pZh, pZl, pCth, pCtl, out, b_out,
        DSTATE, DSTATE, DSTATE, DMODEL, 0);
}